// round 1
// baseline (speedup 1.0000x reference)
#include <cuda_runtime.h>
#include <cuda_bf16.h>
#include <cstdint>
#include <math.h>

// ---------------------------------------------------------------------------
// Problem constants
//   x: (16,4096,512)  y:(16) int32
//   W1:(512,512) b1:(512) W2:(512,512) b2:(512) W3:(512,256) b3:(256)
//   proxies:(3,512)  eps_proxy:(3,128,256)
// Outputs (concatenated f32): mu_topk (16,3,256)=12288, sigma_topk 12288,
//   proxy_loss 1, z (16,4096,256)=16777216  -> total 16801793
// ---------------------------------------------------------------------------
#define B_   16
#define T_   4096
#define XD   512
#define ZD   256
#define HD   512            // 2*ZD
#define CC   3
#define SS   128
#define MTOT (B_*T_)        // 65536
#define OFF_MU    0
#define OFF_SIG   12288
#define OFF_LOSS  24576
#define OFF_Z     24577

// ------------------------- scratch (static device) -------------------------
__device__ float g_h1[(size_t)MTOT * HD];     // 128 MB
__device__ float g_h2[(size_t)MTOT * HD];     // 128 MB
__device__ float g_ps [B_ * 32 * ZD];         // partial col sums
__device__ float g_ps2[B_ * 32 * ZD];         // partial col sumsq
__device__ float g_zsum[B_ * ZD];             // sum_t z_norm
__device__ float g_mu  [CC * ZD];
__device__ float g_sg  [CC * ZD];
__device__ float g_invn[CC * ZD];
__device__ float g_att [B_ * CC * SS];

// ------------------------- SGEMM (fp32, bias, optional relu) ---------------
// C[M,N] = A[M,K] @ B[K,N] + bias[N]   (row-major everywhere)
// BM=128 BN=128 BK=8, 256 threads, 8x8 per-thread tile.
template<bool RELU, bool ALIGNED_STORE>
__global__ __launch_bounds__(256, 2)
void sgemm_bias(const float* __restrict__ A, const float* __restrict__ Bm,
                const float* __restrict__ bias, float* __restrict__ C,
                int M, int N, int K)
{
    constexpr int BM = 128, BN = 128, BK = 8, TM = 8, TN = 8;
    __shared__ float As[BK][BM];
    __shared__ float Bs[BK][BN];

    const int tid = threadIdx.x;
    const int row0 = blockIdx.y * BM;
    const int col0 = blockIdx.x * BN;

    // global->smem load indices (one float4 per thread for each tile)
    const int aRow = tid >> 1;            // 0..127
    const int aCol = (tid & 1) * 4;       // 0 or 4
    const int bRow = tid >> 5;            // 0..7
    const int bCol = (tid & 31) * 4;      // 0..124

    const int tRow = (tid >> 4) * TM;     // 0..120 step 8
    const int tCol = (tid & 15) * TN;     // 0..120 step 8

    float acc[TM][TN];
#pragma unroll
    for (int i = 0; i < TM; i++)
#pragma unroll
        for (int j = 0; j < TN; j++) acc[i][j] = 0.f;

    const float* Aptr = A + (size_t)row0 * K;
    const float* Bptr = Bm + col0;

    for (int k0 = 0; k0 < K; k0 += BK) {
        float4 a4 = *reinterpret_cast<const float4*>(Aptr + (size_t)aRow * K + k0 + aCol);
        As[aCol + 0][aRow] = a4.x;
        As[aCol + 1][aRow] = a4.y;
        As[aCol + 2][aRow] = a4.z;
        As[aCol + 3][aRow] = a4.w;
        *reinterpret_cast<float4*>(&Bs[bRow][bCol]) =
            *reinterpret_cast<const float4*>(Bptr + (size_t)(k0 + bRow) * N + bCol);
        __syncthreads();

#pragma unroll
        for (int kk = 0; kk < BK; kk++) {
            float4 m0 = *reinterpret_cast<const float4*>(&As[kk][tRow]);
            float4 m1 = *reinterpret_cast<const float4*>(&As[kk][tRow + 4]);
            float4 n0 = *reinterpret_cast<const float4*>(&Bs[kk][tCol]);
            float4 n1 = *reinterpret_cast<const float4*>(&Bs[kk][tCol + 4]);
            float rm[TM] = {m0.x, m0.y, m0.z, m0.w, m1.x, m1.y, m1.z, m1.w};
            float rn[TN] = {n0.x, n0.y, n0.z, n0.w, n1.x, n1.y, n1.z, n1.w};
#pragma unroll
            for (int i = 0; i < TM; i++)
#pragma unroll
                for (int j = 0; j < TN; j++)
                    acc[i][j] += rm[i] * rn[j];
        }
        __syncthreads();
    }

    // epilogue
#pragma unroll
    for (int i = 0; i < TM; i++) {
        const size_t row = (size_t)(row0 + tRow + i);
#pragma unroll
        for (int j = 0; j < TN; j += 4) {
            float v0 = acc[i][j + 0] + bias[col0 + tCol + j + 0];
            float v1 = acc[i][j + 1] + bias[col0 + tCol + j + 1];
            float v2 = acc[i][j + 2] + bias[col0 + tCol + j + 2];
            float v3 = acc[i][j + 3] + bias[col0 + tCol + j + 3];
            if (RELU) {
                v0 = fmaxf(v0, 0.f); v1 = fmaxf(v1, 0.f);
                v2 = fmaxf(v2, 0.f); v3 = fmaxf(v3, 0.f);
            }
            float* dst = C + row * N + col0 + tCol + j;
            if (ALIGNED_STORE) {
                *reinterpret_cast<float4*>(dst) = make_float4(v0, v1, v2, v3);
            } else {
                dst[0] = v0; dst[1] = v1; dst[2] = v2; dst[3] = v3;
            }
        }
    }
}

// --------------------- column reductions over t (per b,k) ------------------
// z layout: z[b*T + t][ZD]. Stage 1: 32 t-chunks of 128 each.
__global__ void colreduce_partial(const float* __restrict__ z)
{
    const int b  = blockIdx.x;      // 0..15
    const int tc = blockIdx.y;      // 0..31
    const int k  = threadIdx.x;     // 0..255
    const float* base = z + ((size_t)b * T_ + (size_t)tc * 128) * ZD + k;
    float s = 0.f, s2 = 0.f;
#pragma unroll 4
    for (int i = 0; i < 128; i++) {
        float v = base[(size_t)i * ZD];
        s += v; s2 += v * v;
    }
    g_ps [(b * 32 + tc) * ZD + k] = s;
    g_ps2[(b * 32 + tc) * ZD + k] = s2;
}

__global__ void colreduce_final()
{
    const int b = blockIdx.x, k = threadIdx.x;
    float s = 0.f, s2 = 0.f;
#pragma unroll
    for (int tc = 0; tc < 32; tc++) {
        s  += g_ps [(b * 32 + tc) * ZD + k];
        s2 += g_ps2[(b * 32 + tc) * ZD + k];
    }
    float n = fmaxf(sqrtf(s2), 1e-12f);
    g_zsum[b * ZD + k] = s / n;
}

// --------------------- proxy prep: mu, sigma, 1/||z_proxy||_s --------------
__global__ void proxy_prep(const float* __restrict__ proxies,
                           const float* __restrict__ eps,
                           float* __restrict__ out)
{
    const int c = blockIdx.x;       // 0..2
    const int k = threadIdx.x;      // 0..255
    const float m = proxies[c * 512 + k];
    const float p = proxies[c * 512 + ZD + k];
    const float sg = fmaxf(p, 0.f) + log1pf(expf(-fabsf(p)));   // stable softplus
    g_mu[c * ZD + k] = m;
    g_sg[c * ZD + k] = sg;
    float acc = 0.f;
    const float* e = eps + ((size_t)c * SS) * ZD + k;
#pragma unroll 4
    for (int s = 0; s < SS; s++) {
        float v = m + sg * e[(size_t)s * ZD];
        acc += v * v;
    }
    g_invn[c * ZD + k] = 1.f / fmaxf(sqrtf(acc), 1e-12f);
    // broadcast outputs mu_topk / sigma_topk
    for (int b = 0; b < B_; b++) {
        out[OFF_MU  + (b * CC + c) * ZD + k] = m;
        out[OFF_SIG + (b * CC + c) * ZD + k] = sg;
    }
}

// --------------------- att[b,c,s] -----------------------------------------
__global__ void att_kernel(const float* __restrict__ eps)
{
    const int b = blockIdx.x;       // 0..15
    const int c = blockIdx.y;       // 0..2
    const int s = threadIdx.x;      // 0..127
    const float* e = eps + ((size_t)c * SS + s) * ZD;
    float acc = 0.f;
#pragma unroll 8
    for (int k = 0; k < ZD; k++) {
        float zp = (g_mu[c * ZD + k] + g_sg[c * ZD + k] * e[k]) * g_invn[c * ZD + k];
        acc += g_zsum[b * ZD + k] * zp;
    }
    g_att[(b * CC + c) * SS + s] = acc * (1.f / (float)T_);
}

// --------------------- loss: bitonic top-k, single block -------------------
__device__ inline void sort_desc256(float* d, int tid)
{
#pragma unroll
    for (int k = 2; k <= 256; k <<= 1) {
        for (int j = k >> 1; j > 0; j >>= 1) {
            __syncthreads();
            int ixj = tid ^ j;
            if (ixj > tid) {
                float a = d[tid], b = d[ixj];
                bool up = ((tid & k) == 0);
                if ((a < b) == up) { d[tid] = b; d[ixj] = a; }
            }
        }
    }
    __syncthreads();
}

__global__ void loss_kernel(const int* __restrict__ y, float* __restrict__ out)
{
    __shared__ float buf[256];
    const int tid = threadIdx.x;
    float total = 0.f;      // meaningful on tid 0 only
    float negmean = 0.f;    // meaningful on tid 0 only
    for (int b = 0; b < B_; b++) {
        const int yb = y[b];
        // negatives: the two classes != yb (order irrelevant for top-k)
        const int c0 = (yb == 0) ? 1 : 0;
        const int c1 = (yb == 2) ? 1 : 2;
        const int cneg = (tid < 128) ? c0 : c1;
        buf[tid] = g_att[(b * CC + cneg) * SS + (tid & 127)];
        __syncthreads();
        sort_desc256(buf, tid);
        if (tid == 0) {
            float s = 0.f;
            for (int i = 0; i < 100; i++) s += buf[i];
            negmean = s * 0.01f;
        }
        __syncthreads();
        // positives: att[b, yb, :] padded with -inf
        buf[tid] = (tid < 128) ? g_att[(b * CC + yb) * SS + tid] : -3.4e38f;
        __syncthreads();
        sort_desc256(buf, tid);
        if (tid == 0) {
            float s = 0.f;
            for (int i = 0; i < 100; i++) s += buf[i];
            float posmean = s * 0.01f;
            total += expf(-posmean + negmean);
        }
        __syncthreads();
    }
    if (tid == 0) out[OFF_LOSS] = total / (float)B_;
}

// ---------------------------------------------------------------------------
extern "C" void kernel_launch(void* const* d_in, const int* in_sizes, int n_in,
                              void* d_out, int out_size)
{
    const float* x       = (const float*)d_in[0];
    const int*   y       = (const int*)  d_in[1];
    const float* W1      = (const float*)d_in[2];
    const float* b1      = (const float*)d_in[3];
    const float* W2      = (const float*)d_in[4];
    const float* b2      = (const float*)d_in[5];
    const float* W3      = (const float*)d_in[6];
    const float* b3      = (const float*)d_in[7];
    const float* proxies = (const float*)d_in[8];
    const float* eps     = (const float*)d_in[9];
    float* out = (float*)d_out;

    float* h1; cudaGetSymbolAddress((void**)&h1, g_h1);
    float* h2; cudaGetSymbolAddress((void**)&h2, g_h2);
    float* z = out + OFF_Z;   // 4-byte aligned only -> scalar stores in GEMM3

    // encoder
    sgemm_bias<true,  true ><<<dim3(HD / 128, MTOT / 128), 256>>>(x,  W1, b1, h1, MTOT, HD, XD);
    sgemm_bias<true,  true ><<<dim3(HD / 128, MTOT / 128), 256>>>(h1, W2, b2, h2, MTOT, HD, HD);
    sgemm_bias<false, false><<<dim3(ZD / 128, MTOT / 128), 256>>>(h2, W3, b3, z,  MTOT, ZD, HD);

    // column reductions over t
    colreduce_partial<<<dim3(B_, 32), ZD>>>(z);
    colreduce_final<<<B_, ZD>>>();

    // proxy side + broadcast outputs
    proxy_prep<<<CC, ZD>>>(proxies, eps, out);
    att_kernel<<<dim3(B_, CC), SS>>>(eps);
    loss_kernel<<<1, 256>>>(y, out);
}

// round 2
// speedup vs baseline: 1.9021x; 1.9021x over previous
#include <cuda_runtime.h>
#include <cuda_bf16.h>
#include <cstdint>
#include <math.h>

// ---------------------------------------------------------------------------
//   x: (16,4096,512)  y:(16) int32
//   W1:(512,512) b1:(512) W2:(512,512) b2:(512) W3:(512,256) b3:(256)
//   proxies:(3,512)  eps_proxy:(3,128,256)
// Outputs (f32 concat): mu(12288) sigma(12288) loss(1) z(16*4096*256)
// ---------------------------------------------------------------------------
#define B_   16
#define T_   4096
#define XD   512
#define ZD   256
#define HD   512
#define CC   3
#define SS   128
#define MTOT (B_*T_)        // 65536
#define OFF_MU    0
#define OFF_SIG   12288
#define OFF_LOSS  24576
#define OFF_Z     24577

// ------------------------- scratch (static device) -------------------------
__device__ __nv_bfloat16 g_xh [(size_t)MTOT * XD];
__device__ __nv_bfloat16 g_xl [(size_t)MTOT * XD];
__device__ __nv_bfloat16 g_h1h[(size_t)MTOT * HD];
__device__ __nv_bfloat16 g_h1l[(size_t)MTOT * HD];
__device__ __nv_bfloat16 g_h2h[(size_t)MTOT * HD];
__device__ __nv_bfloat16 g_h2l[(size_t)MTOT * HD];
__device__ __nv_bfloat16 g_w1h[HD * XD], g_w1l[HD * XD];   // [N][K]
__device__ __nv_bfloat16 g_w2h[HD * HD], g_w2l[HD * HD];
__device__ __nv_bfloat16 g_w3h[ZD * HD], g_w3l[ZD * HD];
__device__ float g_ps  [B_ * 32 * ZD];
__device__ float g_ps2 [B_ * 32 * ZD];
__device__ float g_zsum[B_ * ZD];
__device__ float g_mu  [CC * ZD];
__device__ float g_sg  [CC * ZD];
__device__ float g_invn[CC * ZD];
__device__ float g_att [B_ * CC * SS];

// ------------------------- helpers -----------------------------------------
__device__ __forceinline__ void cpasync16(void* s, const void* g) {
    uint32_t sa = (uint32_t)__cvta_generic_to_shared(s);
    asm volatile("cp.async.cg.shared.global [%0], [%1], 16;\n" :: "r"(sa), "l"(g));
}
__device__ __forceinline__ void cp_commit() { asm volatile("cp.async.commit_group;\n"); }
__device__ __forceinline__ void cp_wait1()  { asm volatile("cp.async.wait_group 1;\n"); }

__device__ __forceinline__ void ldmx4(uint32_t& r0, uint32_t& r1, uint32_t& r2, uint32_t& r3,
                                      const __nv_bfloat16* p) {
    uint32_t sa = (uint32_t)__cvta_generic_to_shared(p);
    asm volatile("ldmatrix.sync.aligned.m8n8.x4.shared.b16 {%0,%1,%2,%3}, [%4];\n"
                 : "=r"(r0), "=r"(r1), "=r"(r2), "=r"(r3) : "r"(sa));
}
__device__ __forceinline__ void mma16816(float* d, const uint32_t* a, const uint32_t* b) {
    asm volatile("mma.sync.aligned.m16n8k16.row.col.f32.bf16.bf16.f32 "
                 "{%0,%1,%2,%3}, {%4,%5,%6,%7}, {%8,%9}, {%0,%1,%2,%3};\n"
                 : "+f"(d[0]), "+f"(d[1]), "+f"(d[2]), "+f"(d[3])
                 : "r"(a[0]), "r"(a[1]), "r"(a[2]), "r"(a[3]), "r"(b[0]), "r"(b[1]));
}

// ------------------------- split-2 bf16 GEMM --------------------------------
// C[M,N] = A[M,K] @ Wt[N,K]^T + bias  (A given as hi/lo bf16, Wt as hi/lo bf16)
// OUTMODE 0: relu, write hi/lo bf16 pair.  OUTMODE 1: no relu, write fp32.
template<int OUTMODE>
__global__ __launch_bounds__(256)
void gemm_split2(const __nv_bfloat16* __restrict__ Ah, const __nv_bfloat16* __restrict__ Al,
                 const __nv_bfloat16* __restrict__ Bh, const __nv_bfloat16* __restrict__ Bl,
                 const float* __restrict__ bias,
                 __nv_bfloat16* __restrict__ Oh, __nv_bfloat16* __restrict__ Ol,
                 float* __restrict__ Of, int M, int N, int K)
{
    constexpr int BM = 128, BN = 128, BK = 32;
    constexpr int SA = 40;                 // padded row stride (bf16 elems)
    constexpr int TILE = 128 * SA;         // 5120 elems per sub-tile
    extern __shared__ __align__(16) __nv_bfloat16 sm[];
    // stage s: [Ah | Al | Bh | Bl], each TILE elems
    auto smAh = [&](int s) { return sm + (size_t)s * 4 * TILE; };
    auto smAl = [&](int s) { return sm + (size_t)s * 4 * TILE + TILE; };
    auto smBh = [&](int s) { return sm + (size_t)s * 4 * TILE + 2 * TILE; };
    auto smBl = [&](int s) { return sm + (size_t)s * 4 * TILE + 3 * TILE; };

    const int tid  = threadIdx.x;
    const int lane = tid & 31;
    const int wid  = tid >> 5;
    const int m0w  = (wid >> 2) * 64;      // warp row offset (0 / 64)
    const int n0w  = (wid & 3) * 32;       // warp col offset (0..96)
    const int row0 = blockIdx.y * BM;
    const int col0 = blockIdx.x * BN;

    float acc[4][4][4];
#pragma unroll
    for (int i = 0; i < 4; i++)
#pragma unroll
        for (int j = 0; j < 4; j++)
#pragma unroll
            for (int r = 0; r < 4; r++) acc[i][j][r] = 0.f;

    auto load_stage = [&](int s, int kc) {
        const int k0 = kc * BK;
#pragma unroll
        for (int i = 0; i < 2; i++) {
            int idx = tid + i * 256;       // 0..511
            int r = idx >> 2, sg = (idx & 3) * 8;
            cpasync16(smAh(s) + r * SA + sg, Ah + (size_t)(row0 + r) * K + k0 + sg);
            cpasync16(smAl(s) + r * SA + sg, Al + (size_t)(row0 + r) * K + k0 + sg);
            cpasync16(smBh(s) + r * SA + sg, Bh + (size_t)(col0 + r) * K + k0 + sg);
            cpasync16(smBl(s) + r * SA + sg, Bl + (size_t)(col0 + r) * K + k0 + sg);
        }
    };

    const int nk = K / BK;                 // 16
    load_stage(0, 0); cp_commit();
    load_stage(1, 1); cp_commit();

    for (int kc = 0; kc < nk; kc++) {
        cp_wait1();
        __syncthreads();
        if (kc + 2 < nk) load_stage((kc + 2) % 3, kc + 2);
        cp_commit();

        const int st = kc % 3;
#pragma unroll
        for (int ks = 0; ks < 2; ks++) {
            const int k0s = ks * 16;
            uint32_t ah[4][4], al[4][4], bh[4][2], bl[4][2];
#pragma unroll
            for (int mi = 0; mi < 4; mi++) {
                const int off = (m0w + mi * 16 + (lane & 15)) * SA + k0s + (lane >> 4) * 8;
                ldmx4(ah[mi][0], ah[mi][1], ah[mi][2], ah[mi][3], smAh(st) + off);
                ldmx4(al[mi][0], al[mi][1], al[mi][2], al[mi][3], smAl(st) + off);
            }
#pragma unroll
            for (int nt = 0; nt < 2; nt++) {
                const int off = (n0w + nt * 16 + (lane & 7) + ((lane >> 4) << 3)) * SA
                              + k0s + (((lane >> 3) & 1) << 3);
                uint32_t r0, r1, r2, r3;
                ldmx4(r0, r1, r2, r3, smBh(st) + off);
                bh[nt * 2][0] = r0; bh[nt * 2][1] = r1;
                bh[nt * 2 + 1][0] = r2; bh[nt * 2 + 1][1] = r3;
                ldmx4(r0, r1, r2, r3, smBl(st) + off);
                bl[nt * 2][0] = r0; bl[nt * 2][1] = r1;
                bl[nt * 2 + 1][0] = r2; bl[nt * 2 + 1][1] = r3;
            }
#pragma unroll
            for (int mi = 0; mi < 4; mi++)
#pragma unroll
                for (int nj = 0; nj < 4; nj++) {
                    mma16816(acc[mi][nj], ah[mi], bh[nj]);   // hi*hi
                    mma16816(acc[mi][nj], ah[mi], bl[nj]);   // hi*lo
                    mma16816(acc[mi][nj], al[mi], bh[nj]);   // lo*hi
                }
        }
        __syncthreads();
    }

    // ---------------- epilogue ----------------
    float bv[4][2];
#pragma unroll
    for (int nj = 0; nj < 4; nj++) {
        const int c = col0 + n0w + nj * 8 + (lane & 3) * 2;
        bv[nj][0] = bias[c]; bv[nj][1] = bias[c + 1];
    }
#pragma unroll
    for (int mi = 0; mi < 4; mi++) {
        const int r0 = row0 + m0w + mi * 16 + (lane >> 2);
        const int r1 = r0 + 8;
#pragma unroll
        for (int nj = 0; nj < 4; nj++) {
            const int c = col0 + n0w + nj * 8 + (lane & 3) * 2;
            float v00 = acc[mi][nj][0] + bv[nj][0];
            float v01 = acc[mi][nj][1] + bv[nj][1];
            float v10 = acc[mi][nj][2] + bv[nj][0];
            float v11 = acc[mi][nj][3] + bv[nj][1];
            if (OUTMODE == 0) {
                v00 = fmaxf(v00, 0.f); v01 = fmaxf(v01, 0.f);
                v10 = fmaxf(v10, 0.f); v11 = fmaxf(v11, 0.f);
                __nv_bfloat162 h0, h1, l0, l1;
                h0.x = __float2bfloat16(v00); h0.y = __float2bfloat16(v01);
                h1.x = __float2bfloat16(v10); h1.y = __float2bfloat16(v11);
                l0.x = __float2bfloat16(v00 - __bfloat162float(h0.x));
                l0.y = __float2bfloat16(v01 - __bfloat162float(h0.y));
                l1.x = __float2bfloat16(v10 - __bfloat162float(h1.x));
                l1.y = __float2bfloat16(v11 - __bfloat162float(h1.y));
                *reinterpret_cast<__nv_bfloat162*>(Oh + (size_t)r0 * N + c) = h0;
                *reinterpret_cast<__nv_bfloat162*>(Oh + (size_t)r1 * N + c) = h1;
                *reinterpret_cast<__nv_bfloat162*>(Ol + (size_t)r0 * N + c) = l0;
                *reinterpret_cast<__nv_bfloat162*>(Ol + (size_t)r1 * N + c) = l1;
            } else {
                Of[(size_t)r0 * N + c]     = v00;
                Of[(size_t)r0 * N + c + 1] = v01;
                Of[(size_t)r1 * N + c]     = v10;
                Of[(size_t)r1 * N + c + 1] = v11;
            }
        }
    }
}

// ------------------- conversion kernels ------------------------------------
__global__ void conv_x(const float* __restrict__ x,
                       __nv_bfloat16* __restrict__ xh, __nv_bfloat16* __restrict__ xl)
{
    const size_t i = (size_t)blockIdx.x * blockDim.x + threadIdx.x;   // per 4 elems
    float4 v = reinterpret_cast<const float4*>(x)[i];
    __nv_bfloat162 h0, h1, l0, l1;
    h0.x = __float2bfloat16(v.x); h0.y = __float2bfloat16(v.y);
    h1.x = __float2bfloat16(v.z); h1.y = __float2bfloat16(v.w);
    l0.x = __float2bfloat16(v.x - __bfloat162float(h0.x));
    l0.y = __float2bfloat16(v.y - __bfloat162float(h0.y));
    l1.x = __float2bfloat16(v.z - __bfloat162float(h1.x));
    l1.y = __float2bfloat16(v.w - __bfloat162float(h1.y));
    reinterpret_cast<__nv_bfloat162*>(xh)[i * 2]     = h0;
    reinterpret_cast<__nv_bfloat162*>(xh)[i * 2 + 1] = h1;
    reinterpret_cast<__nv_bfloat162*>(xl)[i * 2]     = l0;
    reinterpret_cast<__nv_bfloat162*>(xl)[i * 2 + 1] = l1;
}

// W[K,N] fp32 -> Wt[N,K] hi/lo bf16 (coalesced reads)
__global__ void conv_w(const float* __restrict__ W,
                       __nv_bfloat16* __restrict__ Wh, __nv_bfloat16* __restrict__ Wl,
                       int K, int N)
{
    const int i = blockIdx.x * blockDim.x + threadIdx.x;
    if (i >= K * N) return;
    const int k = i / N, n = i % N;
    const float v = W[i];
    __nv_bfloat16 h = __float2bfloat16(v);
    __nv_bfloat16 l = __float2bfloat16(v - __bfloat162float(h));
    Wh[(size_t)n * K + k] = h;
    Wl[(size_t)n * K + k] = l;
}

// --------------------- column reductions over t (per b,k) ------------------
__global__ void colreduce_partial(const float* __restrict__ z)
{
    const int b  = blockIdx.x;
    const int tc = blockIdx.y;
    const int k  = threadIdx.x;
    const float* base = z + ((size_t)b * T_ + (size_t)tc * 128) * ZD + k;
    float s = 0.f, s2 = 0.f;
#pragma unroll 4
    for (int i = 0; i < 128; i++) {
        float v = base[(size_t)i * ZD];
        s += v; s2 += v * v;
    }
    g_ps [(b * 32 + tc) * ZD + k] = s;
    g_ps2[(b * 32 + tc) * ZD + k] = s2;
}

__global__ void colreduce_final()
{
    const int b = blockIdx.x, k = threadIdx.x;
    float s = 0.f, s2 = 0.f;
#pragma unroll
    for (int tc = 0; tc < 32; tc++) {
        s  += g_ps [(b * 32 + tc) * ZD + k];
        s2 += g_ps2[(b * 32 + tc) * ZD + k];
    }
    float n = fmaxf(sqrtf(s2), 1e-12f);
    g_zsum[b * ZD + k] = s / n;
}

// --------------------- proxy prep ------------------------------------------
__global__ void proxy_prep(const float* __restrict__ proxies,
                           const float* __restrict__ eps,
                           float* __restrict__ out)
{
    const int c = blockIdx.x;
    const int k = threadIdx.x;
    const float m = proxies[c * 512 + k];
    const float p = proxies[c * 512 + ZD + k];
    const float sg = fmaxf(p, 0.f) + log1pf(expf(-fabsf(p)));
    g_mu[c * ZD + k] = m;
    g_sg[c * ZD + k] = sg;
    float acc = 0.f;
    const float* e = eps + ((size_t)c * SS) * ZD + k;
#pragma unroll 4
    for (int s = 0; s < SS; s++) {
        float v = m + sg * e[(size_t)s * ZD];
        acc += v * v;
    }
    g_invn[c * ZD + k] = 1.f / fmaxf(sqrtf(acc), 1e-12f);
    for (int b = 0; b < B_; b++) {
        out[OFF_MU  + (b * CC + c) * ZD + k] = m;
        out[OFF_SIG + (b * CC + c) * ZD + k] = sg;
    }
}

// --------------------- att[b,c,s] ------------------------------------------
__global__ void att_kernel(const float* __restrict__ eps)
{
    const int b = blockIdx.x;
    const int c = blockIdx.y;
    const int s = threadIdx.x;
    const float* e = eps + ((size_t)c * SS + s) * ZD;
    float acc = 0.f;
#pragma unroll 8
    for (int k = 0; k < ZD; k++) {
        float zp = (g_mu[c * ZD + k] + g_sg[c * ZD + k] * e[k]) * g_invn[c * ZD + k];
        acc += g_zsum[b * ZD + k] * zp;
    }
    g_att[(b * CC + c) * SS + s] = acc * (1.f / (float)T_);
}

// --------------------- loss: bitonic top-k ---------------------------------
__device__ inline void sort_desc256(float* d, int tid)
{
#pragma unroll
    for (int k = 2; k <= 256; k <<= 1) {
        for (int j = k >> 1; j > 0; j >>= 1) {
            __syncthreads();
            int ixj = tid ^ j;
            if (ixj > tid) {
                float a = d[tid], b = d[ixj];
                bool up = ((tid & k) == 0);
                if ((a < b) == up) { d[tid] = b; d[ixj] = a; }
            }
        }
    }
    __syncthreads();
}

__global__ void loss_kernel(const int* __restrict__ y, float* __restrict__ out)
{
    __shared__ float buf[256];
    const int tid = threadIdx.x;
    float total = 0.f;
    float negmean = 0.f;
    for (int b = 0; b < B_; b++) {
        const int yb = y[b];
        const int c0 = (yb == 0) ? 1 : 0;
        const int c1 = (yb == 2) ? 1 : 2;
        const int cneg = (tid < 128) ? c0 : c1;
        buf[tid] = g_att[(b * CC + cneg) * SS + (tid & 127)];
        __syncthreads();
        sort_desc256(buf, tid);
        if (tid == 0) {
            float s = 0.f;
            for (int i = 0; i < 100; i++) s += buf[i];
            negmean = s * 0.01f;
        }
        __syncthreads();
        buf[tid] = (tid < 128) ? g_att[(b * CC + yb) * SS + tid] : -3.4e38f;
        __syncthreads();
        sort_desc256(buf, tid);
        if (tid == 0) {
            float s = 0.f;
            for (int i = 0; i < 100; i++) s += buf[i];
            total += expf(-s * 0.01f + negmean);
        }
        __syncthreads();
    }
    if (tid == 0) out[OFF_LOSS] = total / (float)B_;
}

// ---------------------------------------------------------------------------
extern "C" void kernel_launch(void* const* d_in, const int* in_sizes, int n_in,
                              void* d_out, int out_size)
{
    const float* x       = (const float*)d_in[0];
    const int*   y       = (const int*)  d_in[1];
    const float* W1      = (const float*)d_in[2];
    const float* b1      = (const float*)d_in[3];
    const float* W2      = (const float*)d_in[4];
    const float* b2      = (const float*)d_in[5];
    const float* W3      = (const float*)d_in[6];
    const float* b3      = (const float*)d_in[7];
    const float* proxies = (const float*)d_in[8];
    const float* eps     = (const float*)d_in[9];
    float* out = (float*)d_out;

    __nv_bfloat16 *xh, *xl, *h1h, *h1l, *h2h, *h2l, *w1h, *w1l, *w2h, *w2l, *w3h, *w3l;
    cudaGetSymbolAddress((void**)&xh,  g_xh);  cudaGetSymbolAddress((void**)&xl,  g_xl);
    cudaGetSymbolAddress((void**)&h1h, g_h1h); cudaGetSymbolAddress((void**)&h1l, g_h1l);
    cudaGetSymbolAddress((void**)&h2h, g_h2h); cudaGetSymbolAddress((void**)&h2l, g_h2l);
    cudaGetSymbolAddress((void**)&w1h, g_w1h); cudaGetSymbolAddress((void**)&w1l, g_w1l);
    cudaGetSymbolAddress((void**)&w2h, g_w2h); cudaGetSymbolAddress((void**)&w2l, g_w2l);
    cudaGetSymbolAddress((void**)&w3h, g_w3h); cudaGetSymbolAddress((void**)&w3l, g_w3l);
    float* z = out + OFF_Z;

    const int SMEM = 3 * 4 * 128 * 40 * (int)sizeof(__nv_bfloat16);   // 122880
    cudaFuncSetAttribute(gemm_split2<0>, cudaFuncAttributeMaxDynamicSharedMemorySize, SMEM);
    cudaFuncSetAttribute(gemm_split2<1>, cudaFuncAttributeMaxDynamicSharedMemorySize, SMEM);

    // conversions
    conv_x<<<(MTOT * XD / 4) / 256, 256>>>(x, xh, xl);
    conv_w<<<(XD * HD + 255) / 256, 256>>>(W1, w1h, w1l, XD, HD);
    conv_w<<<(HD * HD + 255) / 256, 256>>>(W2, w2h, w2l, HD, HD);
    conv_w<<<(HD * ZD + 255) / 256, 256>>>(W3, w3h, w3l, HD, ZD);

    // encoder (tensor cores, split-2)
    gemm_split2<0><<<dim3(HD / 128, MTOT / 128), 256, SMEM>>>(
        xh, xl, w1h, w1l, b1, h1h, h1l, nullptr, MTOT, HD, XD);
    gemm_split2<0><<<dim3(HD / 128, MTOT / 128), 256, SMEM>>>(
        h1h, h1l, w2h, w2l, b2, h2h, h2l, nullptr, MTOT, HD, HD);
    gemm_split2<1><<<dim3(ZD / 128, MTOT / 128), 256, SMEM>>>(
        h2h, h2l, w3h, w3l, b3, nullptr, nullptr, z, MTOT, ZD, HD);

    // reductions + proxy side
    colreduce_partial<<<dim3(B_, 32), ZD>>>(z);
    colreduce_final<<<B_, ZD>>>();
    proxy_prep<<<CC, ZD>>>(proxies, eps, out);
    att_kernel<<<dim3(B_, CC), SS>>>(eps);
    loss_kernel<<<1, 256>>>(y, out);
}

// round 4
// speedup vs baseline: 2.0610x; 1.0835x over previous
#include <cuda_runtime.h>
#include <cuda_bf16.h>
#include <cstdint>
#include <math.h>

// ---------------------------------------------------------------------------
//   x: (16,4096,512)  y:(16) int32
//   W1:(512,512) b1:(512) W2:(512,512) b2:(512) W3:(512,256) b3:(256)
//   proxies:(3,512)  eps_proxy:(3,128,256)
// Outputs (f32 concat): mu(12288) sigma(12288) loss(1) z(16*4096*256)
// ---------------------------------------------------------------------------
#define B_   16
#define T_   4096
#define XD   512
#define ZD   256
#define HD   512
#define CC   3
#define SS   128
#define MTOT (B_*T_)        // 65536
#define OFF_MU    0
#define OFF_SIG   12288
#define OFF_LOSS  24576
#define OFF_Z     24577

// ------------------------- scratch (static device) -------------------------
__device__ __nv_bfloat16 g_xh [(size_t)MTOT * XD];
__device__ __nv_bfloat16 g_xl [(size_t)MTOT * XD];
__device__ __nv_bfloat16 g_h1h[(size_t)MTOT * HD];
__device__ __nv_bfloat16 g_h1l[(size_t)MTOT * HD];
__device__ __nv_bfloat16 g_h2h[(size_t)MTOT * HD];
__device__ __nv_bfloat16 g_h2l[(size_t)MTOT * HD];
__device__ __nv_bfloat16 g_w1h[HD * XD], g_w1l[HD * XD];   // [N][K]
__device__ __nv_bfloat16 g_w2h[HD * HD], g_w2l[HD * HD];
__device__ __nv_bfloat16 g_w3h[ZD * HD], g_w3l[ZD * HD];
__device__ float g_ps  [B_ * 32 * ZD];
__device__ float g_ps2 [B_ * 32 * ZD];
__device__ float g_zsum[B_ * ZD];
__device__ float g_mu  [CC * ZD];
__device__ float g_sg  [CC * ZD];
__device__ float g_invn[CC * ZD];
__device__ float g_att [B_ * CC * SS];

// ------------------------- helpers -----------------------------------------
__device__ __forceinline__ void cpasync16(void* s, const void* g) {
    uint32_t sa = (uint32_t)__cvta_generic_to_shared(s);
    asm volatile("cp.async.cg.shared.global [%0], [%1], 16;\n" :: "r"(sa), "l"(g));
}
__device__ __forceinline__ void cp_commit() { asm volatile("cp.async.commit_group;\n"); }
__device__ __forceinline__ void cp_wait1()  { asm volatile("cp.async.wait_group 1;\n"); }
__device__ __forceinline__ void cp_wait0()  { asm volatile("cp.async.wait_group 0;\n"); }

__device__ __forceinline__ void ldmx4(uint32_t& r0, uint32_t& r1, uint32_t& r2, uint32_t& r3,
                                      const __nv_bfloat16* p) {
    uint32_t sa = (uint32_t)__cvta_generic_to_shared(p);
    asm volatile("ldmatrix.sync.aligned.m8n8.x4.shared.b16 {%0,%1,%2,%3}, [%4];\n"
                 : "=r"(r0), "=r"(r1), "=r"(r2), "=r"(r3) : "r"(sa));
}
__device__ __forceinline__ void mma16816(float* d, const uint32_t* a, const uint32_t* b) {
    asm volatile("mma.sync.aligned.m16n8k16.row.col.f32.bf16.bf16.f32 "
                 "{%0,%1,%2,%3}, {%4,%5,%6,%7}, {%8,%9}, {%0,%1,%2,%3};\n"
                 : "+f"(d[0]), "+f"(d[1]), "+f"(d[2]), "+f"(d[3])
                 : "r"(a[0]), "r"(a[1]), "r"(a[2]), "r"(a[3]), "r"(b[0]), "r"(b[1]));
}

// ------------------------- split-2 bf16 GEMM --------------------------------
// C[M,N] = A[M,K] @ Wt[N,K]^T + bias  (A, Wt given as hi/lo bf16 pairs)
// BM=128 BN=256 BK=32, 256 threads = 8 warps of 64x64.
// OUTMODE 0: relu, write hi/lo bf16 pair.  OUTMODE 1: no relu, write fp32.
#define SA    40                       // padded row stride (bf16 elems) = 80 B
#define A_SUB (128 * SA * 2)           // 10240 B per A sub-tile
#define B_SUB (256 * SA * 2)           // 20480 B per B sub-tile
#define STGB  (2 * A_SUB + 2 * B_SUB)  // 61440 B per stage
#define NSTG  3

template<int OUTMODE>
__global__ __launch_bounds__(256, 1)
void gemm_split2(const __nv_bfloat16* __restrict__ Ah, const __nv_bfloat16* __restrict__ Al,
                 const __nv_bfloat16* __restrict__ Bh, const __nv_bfloat16* __restrict__ Bl,
                 const float* __restrict__ bias,
                 __nv_bfloat16* __restrict__ Oh, __nv_bfloat16* __restrict__ Ol,
                 float* __restrict__ Of, int N, int K)
{
    extern __shared__ __align__(16) char sm[];

    const int tid  = threadIdx.x;
    const int lane = tid & 31;
    const int wid  = tid >> 5;
    const int m0w  = (wid >> 2) * 64;      // warp row offset (0 / 64)
    const int n0w  = (wid & 3) * 64;       // warp col offset (0..192)
    const int row0 = blockIdx.y * 128;
    const int col0 = blockIdx.x * 256;

    float acc[4][8][4];
#pragma unroll
    for (int i = 0; i < 4; i++)
#pragma unroll
        for (int j = 0; j < 8; j++)
#pragma unroll
            for (int r = 0; r < 4; r++) acc[i][j][r] = 0.f;

    auto stage_ptr = [&](int s) { return sm + (size_t)s * STGB; };

    auto load_stage = [&](int s, int kc) {
        char* sb = stage_ptr(s);
        const int k0 = kc * 32;
        // A tiles: 128 rows x 4 chunks (16B) = 512 chunks each
#pragma unroll
        for (int i = 0; i < 2; i++) {
            int c = tid + i * 256;
            int r = c >> 2, g = (c & 3) * 16;      // byte offset of chunk in row
            uint32_t so = (uint32_t)(r * (SA * 2) + g);
            cpasync16(sb + so,          Ah + (size_t)(row0 + r) * K + k0 + g / 2);
            cpasync16(sb + A_SUB + so,  Al + (size_t)(row0 + r) * K + k0 + g / 2);
        }
        // B tiles: 256 rows x 4 chunks = 1024 chunks each
#pragma unroll
        for (int i = 0; i < 4; i++) {
            int c = tid + i * 256;
            int r = c >> 2, g = (c & 3) * 16;
            uint32_t so = (uint32_t)(r * (SA * 2) + g);
            cpasync16(sb + 2 * A_SUB + so,         Bh + (size_t)(col0 + r) * K + k0 + g / 2);
            cpasync16(sb + 2 * A_SUB + B_SUB + so, Bl + (size_t)(col0 + r) * K + k0 + g / 2);
        }
        cp_commit();
    };

    const int nk = K / 32;                 // 16
    load_stage(0, 0);
    load_stage(1, 1);

    for (int kc = 0; kc < nk; kc++) {
        if (kc + 2 < nk) cp_wait1(); else cp_wait0();
        __syncthreads();
        if (kc + 2 < nk) load_stage((kc + 2) % NSTG, kc + 2);

        char* sb = stage_ptr(kc % NSTG);
        const __nv_bfloat16* smAh = (const __nv_bfloat16*)(sb);
        const __nv_bfloat16* smAl = (const __nv_bfloat16*)(sb + A_SUB);
        const __nv_bfloat16* smBh = (const __nv_bfloat16*)(sb + 2 * A_SUB);
        const __nv_bfloat16* smBl = (const __nv_bfloat16*)(sb + 2 * A_SUB + B_SUB);

#pragma unroll
        for (int ks = 0; ks < 2; ks++) {
            const int k0s = ks * 16;
            uint32_t ah[4][4], al[4][4], bh[8][2], bl[8][2];
#pragma unroll
            for (int mi = 0; mi < 4; mi++) {
                const int off = (m0w + mi * 16 + (lane & 15)) * SA + k0s + (lane >> 4) * 8;
                ldmx4(ah[mi][0], ah[mi][1], ah[mi][2], ah[mi][3], smAh + off);
                ldmx4(al[mi][0], al[mi][1], al[mi][2], al[mi][3], smAl + off);
            }
#pragma unroll
            for (int nt = 0; nt < 4; nt++) {
                const int off = (n0w + nt * 16 + (lane & 7) + ((lane >> 4) << 3)) * SA
                              + k0s + (((lane >> 3) & 1) << 3);
                uint32_t r0, r1, r2, r3;
                ldmx4(r0, r1, r2, r3, smBh + off);
                bh[nt * 2][0] = r0; bh[nt * 2][1] = r1;
                bh[nt * 2 + 1][0] = r2; bh[nt * 2 + 1][1] = r3;
                ldmx4(r0, r1, r2, r3, smBl + off);
                bl[nt * 2][0] = r0; bl[nt * 2][1] = r1;
                bl[nt * 2 + 1][0] = r2; bl[nt * 2 + 1][1] = r3;
            }
#pragma unroll
            for (int mi = 0; mi < 4; mi++)
#pragma unroll
                for (int nj = 0; nj < 8; nj++) {
                    mma16816(acc[mi][nj], ah[mi], bh[nj]);   // hi*hi
                    mma16816(acc[mi][nj], ah[mi], bl[nj]);   // hi*lo
                    mma16816(acc[mi][nj], al[mi], bh[nj]);   // lo*hi
                }
        }
        __syncthreads();
    }

    // ---------------- epilogue ----------------
    float bv[8][2];
#pragma unroll
    for (int nj = 0; nj < 8; nj++) {
        const int c = col0 + n0w + nj * 8 + (lane & 3) * 2;
        bv[nj][0] = bias[c]; bv[nj][1] = bias[c + 1];
    }
#pragma unroll
    for (int mi = 0; mi < 4; mi++) {
        const int r0 = row0 + m0w + mi * 16 + (lane >> 2);
        const int r1 = r0 + 8;
#pragma unroll
        for (int nj = 0; nj < 8; nj++) {
            const int c = col0 + n0w + nj * 8 + (lane & 3) * 2;
            float v00 = acc[mi][nj][0] + bv[nj][0];
            float v01 = acc[mi][nj][1] + bv[nj][1];
            float v10 = acc[mi][nj][2] + bv[nj][0];
            float v11 = acc[mi][nj][3] + bv[nj][1];
            if (OUTMODE == 0) {
                v00 = fmaxf(v00, 0.f); v01 = fmaxf(v01, 0.f);
                v10 = fmaxf(v10, 0.f); v11 = fmaxf(v11, 0.f);
                __nv_bfloat162 h0, h1, l0, l1;
                h0.x = __float2bfloat16(v00); h0.y = __float2bfloat16(v01);
                h1.x = __float2bfloat16(v10); h1.y = __float2bfloat16(v11);
                l0.x = __float2bfloat16(v00 - __bfloat162float(h0.x));
                l0.y = __float2bfloat16(v01 - __bfloat162float(h0.y));
                l1.x = __float2bfloat16(v10 - __bfloat162float(h1.x));
                l1.y = __float2bfloat16(v11 - __bfloat162float(h1.y));
                *reinterpret_cast<__nv_bfloat162*>(Oh + (size_t)r0 * N + c) = h0;
                *reinterpret_cast<__nv_bfloat162*>(Oh + (size_t)r1 * N + c) = h1;
                *reinterpret_cast<__nv_bfloat162*>(Ol + (size_t)r0 * N + c) = l0;
                *reinterpret_cast<__nv_bfloat162*>(Ol + (size_t)r1 * N + c) = l1;
            } else {
                Of[(size_t)r0 * N + c]     = v00;
                Of[(size_t)r0 * N + c + 1] = v01;
                Of[(size_t)r1 * N + c]     = v10;
                Of[(size_t)r1 * N + c + 1] = v11;
            }
        }
    }
}

// ------------------- conversion kernels ------------------------------------
__global__ void conv_x(const float* __restrict__ x,
                       __nv_bfloat16* __restrict__ xh, __nv_bfloat16* __restrict__ xl)
{
    const size_t i = (size_t)blockIdx.x * blockDim.x + threadIdx.x;   // per 4 elems
    float4 v = reinterpret_cast<const float4*>(x)[i];
    __nv_bfloat162 h0, h1, l0, l1;
    h0.x = __float2bfloat16(v.x); h0.y = __float2bfloat16(v.y);
    h1.x = __float2bfloat16(v.z); h1.y = __float2bfloat16(v.w);
    l0.x = __float2bfloat16(v.x - __bfloat162float(h0.x));
    l0.y = __float2bfloat16(v.y - __bfloat162float(h0.y));
    l1.x = __float2bfloat16(v.z - __bfloat162float(h1.x));
    l1.y = __float2bfloat16(v.w - __bfloat162float(h1.y));
    reinterpret_cast<__nv_bfloat162*>(xh)[i * 2]     = h0;
    reinterpret_cast<__nv_bfloat162*>(xh)[i * 2 + 1] = h1;
    reinterpret_cast<__nv_bfloat162*>(xl)[i * 2]     = l0;
    reinterpret_cast<__nv_bfloat162*>(xl)[i * 2 + 1] = l1;
}

// W[K,N] fp32 -> Wt[N,K] hi/lo bf16 (coalesced reads)
__global__ void conv_w(const float* __restrict__ W,
                       __nv_bfloat16* __restrict__ Wh, __nv_bfloat16* __restrict__ Wl,
                       int K, int N)
{
    const int i = blockIdx.x * blockDim.x + threadIdx.x;
    if (i >= K * N) return;
    const int k = i / N, n = i % N;
    const float v = W[i];
    __nv_bfloat16 h = __float2bfloat16(v);
    __nv_bfloat16 l = __float2bfloat16(v - __bfloat162float(h));
    Wh[(size_t)n * K + k] = h;
    Wl[(size_t)n * K + k] = l;
}

// --------------------- column reductions over t (per b,k) ------------------
__global__ void colreduce_partial(const float* __restrict__ z)
{
    const int b  = blockIdx.x;
    const int tc = blockIdx.y;
    const int k  = threadIdx.x;
    const float* base = z + ((size_t)b * T_ + (size_t)tc * 128) * ZD + k;
    float s = 0.f, s2 = 0.f;
#pragma unroll 4
    for (int i = 0; i < 128; i++) {
        float v = base[(size_t)i * ZD];
        s += v; s2 += v * v;
    }
    g_ps [(b * 32 + tc) * ZD + k] = s;
    g_ps2[(b * 32 + tc) * ZD + k] = s2;
}

__global__ void colreduce_final()
{
    const int b = blockIdx.x, k = threadIdx.x;
    float s = 0.f, s2 = 0.f;
#pragma unroll
    for (int tc = 0; tc < 32; tc++) {
        s  += g_ps [(b * 32 + tc) * ZD + k];
        s2 += g_ps2[(b * 32 + tc) * ZD + k];
    }
    float n = fmaxf(sqrtf(s2), 1e-12f);
    g_zsum[b * ZD + k] = s / n;
}

// --------------------- proxy prep ------------------------------------------
__global__ void proxy_prep(const float* __restrict__ proxies,
                           const float* __restrict__ eps,
                           float* __restrict__ out)
{
    const int c = blockIdx.x;
    const int k = threadIdx.x;
    const float m = proxies[c * 512 + k];
    const float p = proxies[c * 512 + ZD + k];
    const float sg = fmaxf(p, 0.f) + log1pf(expf(-fabsf(p)));
    g_mu[c * ZD + k] = m;
    g_sg[c * ZD + k] = sg;
    float acc = 0.f;
    const float* e = eps + ((size_t)c * SS) * ZD + k;
#pragma unroll 4
    for (int s = 0; s < SS; s++) {
        float v = m + sg * e[(size_t)s * ZD];
        acc += v * v;
    }
    g_invn[c * ZD + k] = 1.f / fmaxf(sqrtf(acc), 1e-12f);
    for (int b = 0; b < B_; b++) {
        out[OFF_MU  + (b * CC + c) * ZD + k] = m;
        out[OFF_SIG + (b * CC + c) * ZD + k] = sg;
    }
}

// --------------------- att[b,c,s] ------------------------------------------
__global__ void att_kernel(const float* __restrict__ eps)
{
    const int b = blockIdx.x;
    const int c = blockIdx.y;
    const int s = threadIdx.x;
    const float* e = eps + ((size_t)c * SS + s) * ZD;
    float acc = 0.f;
#pragma unroll 8
    for (int k = 0; k < ZD; k++) {
        float zp = (g_mu[c * ZD + k] + g_sg[c * ZD + k] * e[k]) * g_invn[c * ZD + k];
        acc += g_zsum[b * ZD + k] * zp;
    }
    g_att[(b * CC + c) * SS + s] = acc * (1.f / (float)T_);
}

// --------------------- loss: bitonic top-k ---------------------------------
__device__ inline void sort_desc256(float* d, int tid)
{
#pragma unroll
    for (int k = 2; k <= 256; k <<= 1) {
        for (int j = k >> 1; j > 0; j >>= 1) {
            __syncthreads();
            int ixj = tid ^ j;
            if (ixj > tid) {
                float a = d[tid], b = d[ixj];
                bool up = ((tid & k) == 0);
                if ((a < b) == up) { d[tid] = b; d[ixj] = a; }
            }
        }
    }
    __syncthreads();
}

__global__ void loss_kernel(const int* __restrict__ y, float* __restrict__ out)
{
    __shared__ float buf[256];
    const int tid = threadIdx.x;
    float total = 0.f;
    float negmean = 0.f;
    for (int b = 0; b < B_; b++) {
        const int yb = y[b];
        const int c0 = (yb == 0) ? 1 : 0;
        const int c1 = (yb == 2) ? 1 : 2;
        const int cneg = (tid < 128) ? c0 : c1;
        buf[tid] = g_att[(b * CC + cneg) * SS + (tid & 127)];
        __syncthreads();
        sort_desc256(buf, tid);
        if (tid == 0) {
            float s = 0.f;
            for (int i = 0; i < 100; i++) s += buf[i];
            negmean = s * 0.01f;
        }
        __syncthreads();
        buf[tid] = (tid < 128) ? g_att[(b * CC + yb) * SS + tid] : -3.4e38f;
        __syncthreads();
        sort_desc256(buf, tid);
        if (tid == 0) {
            float s = 0.f;
            for (int i = 0; i < 100; i++) s += buf[i];
            total += expf(-s * 0.01f + negmean);
        }
        __syncthreads();
    }
    if (tid == 0) out[OFF_LOSS] = total / (float)B_;
}

// ---------------------------------------------------------------------------
extern "C" void kernel_launch(void* const* d_in, const int* in_sizes, int n_in,
                              void* d_out, int out_size)
{
    const float* x       = (const float*)d_in[0];
    const int*   y       = (const int*)  d_in[1];
    const float* W1      = (const float*)d_in[2];
    const float* b1      = (const float*)d_in[3];
    const float* W2      = (const float*)d_in[4];
    const float* b2      = (const float*)d_in[5];
    const float* W3      = (const float*)d_in[6];
    const float* b3      = (const float*)d_in[7];
    const float* proxies = (const float*)d_in[8];
    const float* eps     = (const float*)d_in[9];
    float* out = (float*)d_out;

    __nv_bfloat16 *xh, *xl, *h1h, *h1l, *h2h, *h2l, *w1h, *w1l, *w2h, *w2l, *w3h, *w3l;
    cudaGetSymbolAddress((void**)&xh,  g_xh);  cudaGetSymbolAddress((void**)&xl,  g_xl);
    cudaGetSymbolAddress((void**)&h1h, g_h1h); cudaGetSymbolAddress((void**)&h1l, g_h1l);
    cudaGetSymbolAddress((void**)&h2h, g_h2h); cudaGetSymbolAddress((void**)&h2l, g_h2l);
    cudaGetSymbolAddress((void**)&w1h, g_w1h); cudaGetSymbolAddress((void**)&w1l, g_w1l);
    cudaGetSymbolAddress((void**)&w2h, g_w2h); cudaGetSymbolAddress((void**)&w2l, g_w2l);
    cudaGetSymbolAddress((void**)&w3h, g_w3h); cudaGetSymbolAddress((void**)&w3l, g_w3l);
    float* z = out + OFF_Z;

    const int SMEM = NSTG * STGB;   // 184320 B
    cudaFuncSetAttribute(gemm_split2<0>, cudaFuncAttributeMaxDynamicSharedMemorySize, SMEM);
    cudaFuncSetAttribute(gemm_split2<1>, cudaFuncAttributeMaxDynamicSharedMemorySize, SMEM);

    // conversions
    conv_x<<<(MTOT * XD / 4) / 256, 256>>>(x, xh, xl);
    conv_w<<<(XD * HD + 255) / 256, 256>>>(W1, w1h, w1l, XD, HD);
    conv_w<<<(HD * HD + 255) / 256, 256>>>(W2, w2h, w2l, HD, HD);
    conv_w<<<(HD * ZD + 255) / 256, 256>>>(W3, w3h, w3l, HD, ZD);

    // encoder (tensor cores, split-2, BN=256)
    gemm_split2<0><<<dim3(HD / 256, MTOT / 128), 256, SMEM>>>(
        xh, xl, w1h, w1l, b1, h1h, h1l, nullptr, HD, XD);
    gemm_split2<0><<<dim3(HD / 256, MTOT / 128), 256, SMEM>>>(
        h1h, h1l, w2h, w2l, b2, h2h, h2l, nullptr, HD, HD);
    gemm_split2<1><<<dim3(ZD / 256, MTOT / 128), 256, SMEM>>>(
        h2h, h2l, w3h, w3l, b3, nullptr, nullptr, z, ZD, HD);

    // reductions + proxy side
    colreduce_partial<<<dim3(B_, 32), ZD>>>(z);
    colreduce_final<<<B_, ZD>>>();
    proxy_prep<<<CC, ZD>>>(proxies, eps, out);
    att_kernel<<<dim3(B_, CC), SS>>>(eps);
    loss_kernel<<<1, 256>>>(y, out);
}

// round 5
// speedup vs baseline: 2.6720x; 1.2965x over previous
#include <cuda_runtime.h>
#include <cuda_fp16.h>
#include <cstdint>
#include <math.h>

// ---------------------------------------------------------------------------
//   x: (16,4096,512)  y:(16) int32
//   W1:(512,512) b1:(512) W2:(512,512) b2:(512) W3:(512,256) b3:(256)
//   proxies:(3,512)  eps_proxy:(3,128,256)
// Outputs (f32 concat): mu(12288) sigma(12288) loss(1) z(16*4096*256)
// ---------------------------------------------------------------------------
#define B_   16
#define T_   4096
#define XD   512
#define ZD   256
#define HD   512
#define CC   3
#define SS   128
#define MTOT (B_*T_)        // 65536
#define OFF_MU    0
#define OFF_SIG   12288
#define OFF_LOSS  24576
#define OFF_Z     24577

// ------------------------- scratch (static device) -------------------------
__device__ __half g_x16[(size_t)MTOT * XD];
__device__ __half g_h1 [(size_t)MTOT * HD];
__device__ __half g_h2 [(size_t)MTOT * HD];
__device__ __half g_w1h[HD * XD], g_w1l[HD * XD];   // [N][K] transposed
__device__ __half g_w2h[HD * HD], g_w2l[HD * HD];
__device__ __half g_w3h[ZD * HD], g_w3l[ZD * HD];
__device__ float g_ps  [B_ * 32 * ZD];
__device__ float g_ps2 [B_ * 32 * ZD];
__device__ float g_zsum[B_ * ZD];
__device__ float g_mu  [CC * ZD];
__device__ float g_sg  [CC * ZD];
__device__ float g_invn[CC * ZD];
__device__ float g_att [B_ * CC * SS];

// ------------------------- helpers -----------------------------------------
__device__ __forceinline__ void cpasync16(void* s, const void* g) {
    uint32_t sa = (uint32_t)__cvta_generic_to_shared(s);
    asm volatile("cp.async.cg.shared.global [%0], [%1], 16;\n" :: "r"(sa), "l"(g));
}
__device__ __forceinline__ void cp_commit() { asm volatile("cp.async.commit_group;\n"); }
__device__ __forceinline__ void cp_wait1()  { asm volatile("cp.async.wait_group 1;\n"); }
__device__ __forceinline__ void cp_wait0()  { asm volatile("cp.async.wait_group 0;\n"); }

__device__ __forceinline__ void ldmx4(uint32_t& r0, uint32_t& r1, uint32_t& r2, uint32_t& r3,
                                      const __half* p) {
    uint32_t sa = (uint32_t)__cvta_generic_to_shared(p);
    asm volatile("ldmatrix.sync.aligned.m8n8.x4.shared.b16 {%0,%1,%2,%3}, [%4];\n"
                 : "=r"(r0), "=r"(r1), "=r"(r2), "=r"(r3) : "r"(sa));
}
__device__ __forceinline__ void mma16816(float* d, const uint32_t* a, const uint32_t* b) {
    asm volatile("mma.sync.aligned.m16n8k16.row.col.f32.f16.f16.f32 "
                 "{%0,%1,%2,%3}, {%4,%5,%6,%7}, {%8,%9}, {%0,%1,%2,%3};\n"
                 : "+f"(d[0]), "+f"(d[1]), "+f"(d[2]), "+f"(d[3])
                 : "r"(a[0]), "r"(a[1]), "r"(a[2]), "r"(a[3]), "r"(b[0]), "r"(b[1]));
}

// ------------------------- fp16 W-split GEMM --------------------------------
// C[M,N] = A[M,K] @ (Wh+Wl)[N,K]^T + bias.  A single fp16, W split hi/lo fp16.
// BM=128 BN=256 BK=32, 256 threads = 8 warps of 64x64.
// OUTMODE 0: relu, write fp16.  OUTMODE 1: no relu, write fp32.
#define SA    40                       // padded row stride (half elems) = 80 B
#define A_SUB (128 * SA * 2)           // 10240 B (single A sub-tile)
#define B_SUB (256 * SA * 2)           // 20480 B per B sub-tile
#define STGB  (A_SUB + 2 * B_SUB)      // 51200 B per stage
#define NSTG  3

template<int OUTMODE>
__global__ __launch_bounds__(256, 1)
void gemm_wsplit(const __half* __restrict__ A,
                 const __half* __restrict__ Bh, const __half* __restrict__ Bl,
                 const float* __restrict__ bias,
                 __half* __restrict__ Oh, float* __restrict__ Of, int N, int K)
{
    extern __shared__ __align__(16) char sm[];

    const int tid  = threadIdx.x;
    const int lane = tid & 31;
    const int wid  = tid >> 5;
    const int m0w  = (wid >> 2) * 64;      // warp row offset (0 / 64)
    const int n0w  = (wid & 3) * 64;       // warp col offset (0..192)
    const int row0 = blockIdx.y * 128;
    const int col0 = blockIdx.x * 256;

    float acc[4][8][4];
#pragma unroll
    for (int i = 0; i < 4; i++)
#pragma unroll
        for (int j = 0; j < 8; j++)
#pragma unroll
            for (int r = 0; r < 4; r++) acc[i][j][r] = 0.f;

    auto stage_ptr = [&](int s) { return sm + (size_t)s * STGB; };

    auto load_stage = [&](int s, int kc) {
        char* sb = stage_ptr(s);
        const int k0 = kc * 32;
        // A tile: 128 rows x 4 chunks (16B)
#pragma unroll
        for (int i = 0; i < 2; i++) {
            int c = tid + i * 256;
            int r = c >> 2, g = (c & 3) * 16;
            uint32_t so = (uint32_t)(r * (SA * 2) + g);
            cpasync16(sb + so, A + (size_t)(row0 + r) * K + k0 + g / 2);
        }
        // B tiles: 256 rows x 4 chunks each
#pragma unroll
        for (int i = 0; i < 4; i++) {
            int c = tid + i * 256;
            int r = c >> 2, g = (c & 3) * 16;
            uint32_t so = (uint32_t)(r * (SA * 2) + g);
            cpasync16(sb + A_SUB + so,         Bh + (size_t)(col0 + r) * K + k0 + g / 2);
            cpasync16(sb + A_SUB + B_SUB + so, Bl + (size_t)(col0 + r) * K + k0 + g / 2);
        }
        cp_commit();
    };

    const int nk = K / 32;                 // 16 or 8
    load_stage(0, 0);
    load_stage(1, 1);

    for (int kc = 0; kc < nk; kc++) {
        if (kc + 2 < nk) cp_wait1(); else cp_wait0();
        __syncthreads();
        if (kc + 2 < nk) load_stage((kc + 2) % NSTG, kc + 2);

        char* sb = stage_ptr(kc % NSTG);
        const __half* smA  = (const __half*)(sb);
        const __half* smBh = (const __half*)(sb + A_SUB);
        const __half* smBl = (const __half*)(sb + A_SUB + B_SUB);

#pragma unroll
        for (int ks = 0; ks < 2; ks++) {
            const int k0s = ks * 16;
            uint32_t a[4][4], bh[8][2], bl[8][2];
#pragma unroll
            for (int mi = 0; mi < 4; mi++) {
                const int off = (m0w + mi * 16 + (lane & 15)) * SA + k0s + (lane >> 4) * 8;
                ldmx4(a[mi][0], a[mi][1], a[mi][2], a[mi][3], smA + off);
            }
#pragma unroll
            for (int nt = 0; nt < 4; nt++) {
                const int off = (n0w + nt * 16 + (lane & 7) + ((lane >> 4) << 3)) * SA
                              + k0s + (((lane >> 3) & 1) << 3);
                uint32_t r0, r1, r2, r3;
                ldmx4(r0, r1, r2, r3, smBh + off);
                bh[nt * 2][0] = r0; bh[nt * 2][1] = r1;
                bh[nt * 2 + 1][0] = r2; bh[nt * 2 + 1][1] = r3;
                ldmx4(r0, r1, r2, r3, smBl + off);
                bl[nt * 2][0] = r0; bl[nt * 2][1] = r1;
                bl[nt * 2 + 1][0] = r2; bl[nt * 2 + 1][1] = r3;
            }
#pragma unroll
            for (int mi = 0; mi < 4; mi++)
#pragma unroll
                for (int nj = 0; nj < 8; nj++) {
                    mma16816(acc[mi][nj], a[mi], bh[nj]);
                    mma16816(acc[mi][nj], a[mi], bl[nj]);
                }
        }
        __syncthreads();
    }

    // ---------------- epilogue ----------------
    float bv[8][2];
#pragma unroll
    for (int nj = 0; nj < 8; nj++) {
        const int c = col0 + n0w + nj * 8 + (lane & 3) * 2;
        bv[nj][0] = bias[c]; bv[nj][1] = bias[c + 1];
    }
#pragma unroll
    for (int mi = 0; mi < 4; mi++) {
        const int r0 = row0 + m0w + mi * 16 + (lane >> 2);
        const int r1 = r0 + 8;
#pragma unroll
        for (int nj = 0; nj < 8; nj++) {
            const int c = col0 + n0w + nj * 8 + (lane & 3) * 2;
            float v00 = acc[mi][nj][0] + bv[nj][0];
            float v01 = acc[mi][nj][1] + bv[nj][1];
            float v10 = acc[mi][nj][2] + bv[nj][0];
            float v11 = acc[mi][nj][3] + bv[nj][1];
            if (OUTMODE == 0) {
                v00 = fmaxf(v00, 0.f); v01 = fmaxf(v01, 0.f);
                v10 = fmaxf(v10, 0.f); v11 = fmaxf(v11, 0.f);
                __half2 h0, h1;
                h0.x = __float2half(v00); h0.y = __float2half(v01);
                h1.x = __float2half(v10); h1.y = __float2half(v11);
                *reinterpret_cast<__half2*>(Oh + (size_t)r0 * N + c) = h0;
                *reinterpret_cast<__half2*>(Oh + (size_t)r1 * N + c) = h1;
            } else {
                Of[(size_t)r0 * N + c]     = v00;
                Of[(size_t)r0 * N + c + 1] = v01;
                Of[(size_t)r1 * N + c]     = v10;
                Of[(size_t)r1 * N + c + 1] = v11;
            }
        }
    }
}

// ------------------- conversion kernels ------------------------------------
__global__ void conv_x(const float* __restrict__ x, __half* __restrict__ x16)
{
    const size_t i = (size_t)blockIdx.x * blockDim.x + threadIdx.x;   // per 4 elems
    float4 v = reinterpret_cast<const float4*>(x)[i];
    __half2 h0, h1;
    h0.x = __float2half(v.x); h0.y = __float2half(v.y);
    h1.x = __float2half(v.z); h1.y = __float2half(v.w);
    reinterpret_cast<__half2*>(x16)[i * 2]     = h0;
    reinterpret_cast<__half2*>(x16)[i * 2 + 1] = h1;
}

// W[K,N] fp32 -> Wt[N,K] hi/lo fp16 (coalesced reads)
__global__ void conv_w(const float* __restrict__ W,
                       __half* __restrict__ Wh, __half* __restrict__ Wl,
                       int K, int N)
{
    const int i = blockIdx.x * blockDim.x + threadIdx.x;
    if (i >= K * N) return;
    const int k = i / N, n = i % N;
    const float v = W[i];
    __half h = __float2half(v);
    __half l = __float2half(v - __half2float(h));
    Wh[(size_t)n * K + k] = h;
    Wl[(size_t)n * K + k] = l;
}

// --------------------- column reductions over t (per b,k) ------------------
__global__ void colreduce_partial(const float* __restrict__ z)
{
    const int b  = blockIdx.x;
    const int tc = blockIdx.y;
    const int k  = threadIdx.x;
    const float* base = z + ((size_t)b * T_ + (size_t)tc * 128) * ZD + k;
    float s = 0.f, s2 = 0.f;
#pragma unroll 4
    for (int i = 0; i < 128; i++) {
        float v = base[(size_t)i * ZD];
        s += v; s2 += v * v;
    }
    g_ps [(b * 32 + tc) * ZD + k] = s;
    g_ps2[(b * 32 + tc) * ZD + k] = s2;
}

__global__ void colreduce_final()
{
    const int b = blockIdx.x, k = threadIdx.x;
    float s = 0.f, s2 = 0.f;
#pragma unroll
    for (int tc = 0; tc < 32; tc++) {
        s  += g_ps [(b * 32 + tc) * ZD + k];
        s2 += g_ps2[(b * 32 + tc) * ZD + k];
    }
    float n = fmaxf(sqrtf(s2), 1e-12f);
    g_zsum[b * ZD + k] = s / n;
}

// --------------------- proxy prep ------------------------------------------
__global__ void proxy_prep(const float* __restrict__ proxies,
                           const float* __restrict__ eps,
                           float* __restrict__ out)
{
    const int c = blockIdx.x;
    const int k = threadIdx.x;
    const float m = proxies[c * 512 + k];
    const float p = proxies[c * 512 + ZD + k];
    const float sg = fmaxf(p, 0.f) + log1pf(expf(-fabsf(p)));
    g_mu[c * ZD + k] = m;
    g_sg[c * ZD + k] = sg;
    float acc = 0.f;
    const float* e = eps + ((size_t)c * SS) * ZD + k;
#pragma unroll 4
    for (int s = 0; s < SS; s++) {
        float v = m + sg * e[(size_t)s * ZD];
        acc += v * v;
    }
    g_invn[c * ZD + k] = 1.f / fmaxf(sqrtf(acc), 1e-12f);
    for (int b = 0; b < B_; b++) {
        out[OFF_MU  + (b * CC + c) * ZD + k] = m;
        out[OFF_SIG + (b * CC + c) * ZD + k] = sg;
    }
}

// --------------------- att[b,c,s] ------------------------------------------
__global__ void att_kernel(const float* __restrict__ eps)
{
    const int b = blockIdx.x;
    const int c = blockIdx.y;
    const int s = threadIdx.x;
    const float* e = eps + ((size_t)c * SS + s) * ZD;
    float acc = 0.f;
#pragma unroll 8
    for (int k = 0; k < ZD; k++) {
        float zp = (g_mu[c * ZD + k] + g_sg[c * ZD + k] * e[k]) * g_invn[c * ZD + k];
        acc += g_zsum[b * ZD + k] * zp;
    }
    g_att[(b * CC + c) * SS + s] = acc * (1.f / (float)T_);
}

// --------------------- loss: bitonic top-k ---------------------------------
__device__ inline void sort_desc256(float* d, int tid)
{
#pragma unroll
    for (int k = 2; k <= 256; k <<= 1) {
        for (int j = k >> 1; j > 0; j >>= 1) {
            __syncthreads();
            int ixj = tid ^ j;
            if (ixj > tid) {
                float a = d[tid], b = d[ixj];
                bool up = ((tid & k) == 0);
                if ((a < b) == up) { d[tid] = b; d[ixj] = a; }
            }
        }
    }
    __syncthreads();
}

__global__ void loss_kernel(const int* __restrict__ y, float* __restrict__ out)
{
    __shared__ float buf[256];
    const int tid = threadIdx.x;
    float total = 0.f;
    float negmean = 0.f;
    for (int b = 0; b < B_; b++) {
        const int yb = y[b];
        const int c0 = (yb == 0) ? 1 : 0;
        const int c1 = (yb == 2) ? 1 : 2;
        const int cneg = (tid < 128) ? c0 : c1;
        buf[tid] = g_att[(b * CC + cneg) * SS + (tid & 127)];
        __syncthreads();
        sort_desc256(buf, tid);
        if (tid == 0) {
            float s = 0.f;
            for (int i = 0; i < 100; i++) s += buf[i];
            negmean = s * 0.01f;
        }
        __syncthreads();
        buf[tid] = (tid < 128) ? g_att[(b * CC + yb) * SS + tid] : -3.4e38f;
        __syncthreads();
        sort_desc256(buf, tid);
        if (tid == 0) {
            float s = 0.f;
            for (int i = 0; i < 100; i++) s += buf[i];
            total += expf(-s * 0.01f + negmean);
        }
        __syncthreads();
    }
    if (tid == 0) out[OFF_LOSS] = total / (float)B_;
}

// ---------------------------------------------------------------------------
extern "C" void kernel_launch(void* const* d_in, const int* in_sizes, int n_in,
                              void* d_out, int out_size)
{
    const float* x       = (const float*)d_in[0];
    const int*   y       = (const int*)  d_in[1];
    const float* W1      = (const float*)d_in[2];
    const float* b1      = (const float*)d_in[3];
    const float* W2      = (const float*)d_in[4];
    const float* b2      = (const float*)d_in[5];
    const float* W3      = (const float*)d_in[6];
    const float* b3      = (const float*)d_in[7];
    const float* proxies = (const float*)d_in[8];
    const float* eps     = (const float*)d_in[9];
    float* out = (float*)d_out;

    __half *x16, *h1, *h2, *w1h, *w1l, *w2h, *w2l, *w3h, *w3l;
    cudaGetSymbolAddress((void**)&x16, g_x16);
    cudaGetSymbolAddress((void**)&h1,  g_h1);
    cudaGetSymbolAddress((void**)&h2,  g_h2);
    cudaGetSymbolAddress((void**)&w1h, g_w1h); cudaGetSymbolAddress((void**)&w1l, g_w1l);
    cudaGetSymbolAddress((void**)&w2h, g_w2h); cudaGetSymbolAddress((void**)&w2l, g_w2l);
    cudaGetSymbolAddress((void**)&w3h, g_w3h); cudaGetSymbolAddress((void**)&w3l, g_w3l);
    float* z = out + OFF_Z;

    const int SMEM = NSTG * STGB;   // 153600 B
    cudaFuncSetAttribute(gemm_wsplit<0>, cudaFuncAttributeMaxDynamicSharedMemorySize, SMEM);
    cudaFuncSetAttribute(gemm_wsplit<1>, cudaFuncAttributeMaxDynamicSharedMemorySize, SMEM);

    // conversions
    conv_x<<<(MTOT * XD / 4) / 256, 256>>>(x, x16);
    conv_w<<<(XD * HD + 255) / 256, 256>>>(W1, w1h, w1l, XD, HD);
    conv_w<<<(HD * HD + 255) / 256, 256>>>(W2, w2h, w2l, HD, HD);
    conv_w<<<(HD * ZD + 255) / 256, 256>>>(W3, w3h, w3l, HD, ZD);

    // encoder (tensor cores, fp16 W-split, 2 passes)
    gemm_wsplit<0><<<dim3(HD / 256, MTOT / 128), 256, SMEM>>>(
        x16, w1h, w1l, b1, h1, nullptr, HD, XD);
    gemm_wsplit<0><<<dim3(HD / 256, MTOT / 128), 256, SMEM>>>(
        h1, w2h, w2l, b2, h2, nullptr, HD, HD);
    gemm_wsplit<1><<<dim3(ZD / 256, MTOT / 128), 256, SMEM>>>(
        h2, w3h, w3l, b3, nullptr, z, ZD, HD);

    // reductions + proxy side
    colreduce_partial<<<dim3(B_, 32), ZD>>>(z);
    colreduce_final<<<B_, ZD>>>();
    proxy_prep<<<CC, ZD>>>(proxies, eps, out);
    att_kernel<<<dim3(B_, CC), SS>>>(eps);
    loss_kernel<<<1, 256>>>(y, out);
}

// round 8
// speedup vs baseline: 3.6779x; 1.3765x over previous
#include <cuda_runtime.h>
#include <cuda_fp16.h>
#include <cstdint>
#include <math.h>

// ---------------------------------------------------------------------------
//   x: (16,4096,512)  y:(16) int32
//   W1:(512,512) b1:(512) W2:(512,512) b2:(512) W3:(512,256) b3:(256)
//   proxies:(3,512)  eps_proxy:(3,128,256)
// Outputs (f32 concat): mu(12288) sigma(12288) loss(1) z(16*4096*256)
// ---------------------------------------------------------------------------
#define B_   16
#define T_   4096
#define XD   512
#define ZD   256
#define HD   512
#define CC   3
#define SS   128
#define MTOT (B_*T_)        // 65536
#define OFF_MU    0
#define OFF_SIG   12288
#define OFF_LOSS  24576
#define OFF_Z     24577

// ------------------------- scratch (static device) -------------------------
__device__ __half g_x16[(size_t)MTOT * XD];
__device__ __half g_h1 [(size_t)MTOT * HD];
__device__ __half g_h2 [(size_t)MTOT * HD];
__device__ __half g_w1 [HD * XD];        // [N][K] transposed
__device__ __half g_w2 [HD * HD];
__device__ __half g_w3 [ZD * HD];
__device__ float g_ps  [B_ * 32 * ZD];
__device__ float g_ps2 [B_ * 32 * ZD];
__device__ float g_zsum[B_ * ZD];
__device__ float g_mu  [CC * ZD];
__device__ float g_sg  [CC * ZD];
__device__ float g_invn[CC * ZD];
__device__ float g_att [B_ * CC * SS];

// ------------------------- helpers -----------------------------------------
__device__ __forceinline__ void cpasync16(void* s, const void* g) {
    uint32_t sa = (uint32_t)__cvta_generic_to_shared(s);
    asm volatile("cp.async.cg.shared.global [%0], [%1], 16;\n" :: "r"(sa), "l"(g));
}
__device__ __forceinline__ void cp_commit() { asm volatile("cp.async.commit_group;\n"); }
__device__ __forceinline__ void cp_wait1()  { asm volatile("cp.async.wait_group 1;\n"); }
__device__ __forceinline__ void cp_wait0()  { asm volatile("cp.async.wait_group 0;\n"); }

__device__ __forceinline__ void ldmx4(uint32_t& r0, uint32_t& r1, uint32_t& r2, uint32_t& r3,
                                      const __half* p) {
    uint32_t sa = (uint32_t)__cvta_generic_to_shared(p);
    asm volatile("ldmatrix.sync.aligned.m8n8.x4.shared.b16 {%0,%1,%2,%3}, [%4];\n"
                 : "=r"(r0), "=r"(r1), "=r"(r2), "=r"(r3) : "r"(sa));
}
__device__ __forceinline__ void mma16816(float* d, const uint32_t* a, const uint32_t* b) {
    asm volatile("mma.sync.aligned.m16n8k16.row.col.f32.f16.f16.f32 "
                 "{%0,%1,%2,%3}, {%4,%5,%6,%7}, {%8,%9}, {%0,%1,%2,%3};\n"
                 : "+f"(d[0]), "+f"(d[1]), "+f"(d[2]), "+f"(d[3])
                 : "r"(a[0]), "r"(a[1]), "r"(a[2]), "r"(a[3]), "r"(b[0]), "r"(b[1]));
}

// ------------------------- fp16 GEMM ----------------------------------------
// C[M,N] = A[M,K] @ W[N,K]^T + bias.   BM=128 BN=256 BK=32, 8 warps of 64x64.
// Pipeline: 3 stages, prefetch +2, wait_group 1 (proven R5 structure).
// OUTMODE 0: relu, write fp16.  OUTMODE 1: no relu, write fp32.
#define SA    40                       // padded row stride (half elems) = 80 B
#define A_SUB (128 * SA * 2)           // 10240 B
#define B_SUB (256 * SA * 2)           // 20480 B
#define STGB  (A_SUB + B_SUB)          // 30720 B per stage
#define NSTG  3

template<int OUTMODE>
__global__ __launch_bounds__(256, 1)
void gemm_f16(const __half* __restrict__ A, const __half* __restrict__ Bw,
              const float* __restrict__ bias,
              __half* __restrict__ Oh, float* __restrict__ Of, int N, int K)
{
    extern __shared__ __align__(16) char sm[];

    const int tid  = threadIdx.x;
    const int lane = tid & 31;
    const int wid  = tid >> 5;
    const int m0w  = (wid >> 2) * 64;      // warp row offset (0 / 64)
    const int n0w  = (wid & 3) * 64;       // warp col offset (0..192)
    const int row0 = blockIdx.y * 128;
    const int col0 = blockIdx.x * 256;

    float acc[4][8][4];
#pragma unroll
    for (int i = 0; i < 4; i++)
#pragma unroll
        for (int j = 0; j < 8; j++)
#pragma unroll
            for (int r = 0; r < 4; r++) acc[i][j][r] = 0.f;

    auto stage_ptr = [&](int s) { return sm + (size_t)s * STGB; };

    auto load_stage = [&](int s, int kc) {
        char* sb = stage_ptr(s);
        const int k0 = kc * 32;
#pragma unroll
        for (int i = 0; i < 2; i++) {
            int c = tid + i * 256;
            int r = c >> 2, g = (c & 3) * 16;
            uint32_t so = (uint32_t)(r * (SA * 2) + g);
            cpasync16(sb + so, A + (size_t)(row0 + r) * K + k0 + g / 2);
        }
#pragma unroll
        for (int i = 0; i < 4; i++) {
            int c = tid + i * 256;
            int r = c >> 2, g = (c & 3) * 16;
            uint32_t so = (uint32_t)(r * (SA * 2) + g);
            cpasync16(sb + A_SUB + so, Bw + (size_t)(col0 + r) * K + k0 + g / 2);
        }
        cp_commit();
    };

    const int nk = K / 32;                 // 16
    load_stage(0, 0);
    load_stage(1, 1);

    for (int kc = 0; kc < nk; kc++) {
        if (kc + 2 < nk) cp_wait1(); else cp_wait0();
        __syncthreads();
        if (kc + 2 < nk) load_stage((kc + 2) % NSTG, kc + 2);

        char* sb = stage_ptr(kc % NSTG);
        const __half* smA = (const __half*)(sb);
        const __half* smB = (const __half*)(sb + A_SUB);

#pragma unroll
        for (int ks = 0; ks < 2; ks++) {
            const int k0s = ks * 16;
            uint32_t a[4][4], b[8][2];
#pragma unroll
            for (int mi = 0; mi < 4; mi++) {
                const int off = (m0w + mi * 16 + (lane & 15)) * SA + k0s + (lane >> 4) * 8;
                ldmx4(a[mi][0], a[mi][1], a[mi][2], a[mi][3], smA + off);
            }
#pragma unroll
            for (int nt = 0; nt < 4; nt++) {
                const int off = (n0w + nt * 16 + (lane & 7) + ((lane >> 4) << 3)) * SA
                              + k0s + (((lane >> 3) & 1) << 3);
                uint32_t r0, r1, r2, r3;
                ldmx4(r0, r1, r2, r3, smB + off);
                b[nt * 2][0] = r0; b[nt * 2][1] = r1;
                b[nt * 2 + 1][0] = r2; b[nt * 2 + 1][1] = r3;
            }
#pragma unroll
            for (int mi = 0; mi < 4; mi++)
#pragma unroll
                for (int nj = 0; nj < 8; nj++)
                    mma16816(acc[mi][nj], a[mi], b[nj]);
        }
        __syncthreads();
    }

    // ---------------- epilogue ----------------
    float bv[8][2];
#pragma unroll
    for (int nj = 0; nj < 8; nj++) {
        const int c = col0 + n0w + nj * 8 + (lane & 3) * 2;
        bv[nj][0] = bias[c]; bv[nj][1] = bias[c + 1];
    }
#pragma unroll
    for (int mi = 0; mi < 4; mi++) {
        const int r0 = row0 + m0w + mi * 16 + (lane >> 2);
        const int r1 = r0 + 8;
#pragma unroll
        for (int nj = 0; nj < 8; nj++) {
            const int c = col0 + n0w + nj * 8 + (lane & 3) * 2;
            float v00 = acc[mi][nj][0] + bv[nj][0];
            float v01 = acc[mi][nj][1] + bv[nj][1];
            float v10 = acc[mi][nj][2] + bv[nj][0];
            float v11 = acc[mi][nj][3] + bv[nj][1];
            if (OUTMODE == 0) {
                v00 = fmaxf(v00, 0.f); v01 = fmaxf(v01, 0.f);
                v10 = fmaxf(v10, 0.f); v11 = fmaxf(v11, 0.f);
                __half2 h0, h1;
                h0.x = __float2half(v00); h0.y = __float2half(v01);
                h1.x = __float2half(v10); h1.y = __float2half(v11);
                *reinterpret_cast<__half2*>(Oh + (size_t)r0 * N + c) = h0;
                *reinterpret_cast<__half2*>(Oh + (size_t)r1 * N + c) = h1;
            } else {
                Of[(size_t)r0 * N + c]     = v00;
                Of[(size_t)r0 * N + c + 1] = v01;
                Of[(size_t)r1 * N + c]     = v10;
                Of[(size_t)r1 * N + c + 1] = v11;
            }
        }
    }
}

// ------------------- conversion kernels ------------------------------------
__global__ void conv_x(const float* __restrict__ x, __half* __restrict__ x16)
{
    const size_t i = (size_t)blockIdx.x * blockDim.x + threadIdx.x;   // per 4 elems
    float4 v = reinterpret_cast<const float4*>(x)[i];
    __half2 h0, h1;
    h0.x = __float2half(v.x); h0.y = __float2half(v.y);
    h1.x = __float2half(v.z); h1.y = __float2half(v.w);
    reinterpret_cast<__half2*>(x16)[i * 2]     = h0;
    reinterpret_cast<__half2*>(x16)[i * 2 + 1] = h1;
}

// W[K,N] fp32 -> Wt[N,K] fp16 (coalesced reads)
__global__ void conv_w(const float* __restrict__ W, __half* __restrict__ Wt,
                       int K, int N)
{
    const int i = blockIdx.x * blockDim.x + threadIdx.x;
    if (i >= K * N) return;
    const int k = i / N, n = i % N;
    Wt[(size_t)n * K + k] = __float2half(W[i]);
}

// --------------------- column reductions over t (per b,k) ------------------
__global__ void colreduce_partial(const float* __restrict__ z)
{
    const int b  = blockIdx.x;
    const int tc = blockIdx.y;
    const int k  = threadIdx.x;
    const float* base = z + ((size_t)b * T_ + (size_t)tc * 128) * ZD + k;
    float s = 0.f, s2 = 0.f;
#pragma unroll 4
    for (int i = 0; i < 128; i++) {
        float v = base[(size_t)i * ZD];
        s += v; s2 += v * v;
    }
    g_ps [(b * 32 + tc) * ZD + k] = s;
    g_ps2[(b * 32 + tc) * ZD + k] = s2;
}

__global__ void colreduce_final()
{
    const int b = blockIdx.x, k = threadIdx.x;
    float s = 0.f, s2 = 0.f;
#pragma unroll
    for (int tc = 0; tc < 32; tc++) {
        s  += g_ps [(b * 32 + tc) * ZD + k];
        s2 += g_ps2[(b * 32 + tc) * ZD + k];
    }
    float n = fmaxf(sqrtf(s2), 1e-12f);
    g_zsum[b * ZD + k] = s / n;
}

// --------------------- proxy prep ------------------------------------------
__global__ void proxy_prep(const float* __restrict__ proxies,
                           const float* __restrict__ eps,
                           float* __restrict__ out)
{
    const int c = blockIdx.x;
    const int k = threadIdx.x;
    const float m = proxies[c * 512 + k];
    const float p = proxies[c * 512 + ZD + k];
    const float sg = fmaxf(p, 0.f) + log1pf(expf(-fabsf(p)));
    g_mu[c * ZD + k] = m;
    g_sg[c * ZD + k] = sg;
    float acc = 0.f;
    const float* e = eps + ((size_t)c * SS) * ZD + k;
#pragma unroll 4
    for (int s = 0; s < SS; s++) {
        float v = m + sg * e[(size_t)s * ZD];
        acc += v * v;
    }
    g_invn[c * ZD + k] = 1.f / fmaxf(sqrtf(acc), 1e-12f);
    for (int b = 0; b < B_; b++) {
        out[OFF_MU  + (b * CC + c) * ZD + k] = m;
        out[OFF_SIG + (b * CC + c) * ZD + k] = sg;
    }
}

// --------------------- att[b,c,s] ------------------------------------------
__global__ void att_kernel(const float* __restrict__ eps)
{
    const int b = blockIdx.x;
    const int c = blockIdx.y;
    const int s = threadIdx.x;
    const float* e = eps + ((size_t)c * SS + s) * ZD;
    float acc = 0.f;
#pragma unroll 8
    for (int k = 0; k < ZD; k++) {
        float zp = (g_mu[c * ZD + k] + g_sg[c * ZD + k] * e[k]) * g_invn[c * ZD + k];
        acc += g_zsum[b * ZD + k] * zp;
    }
    g_att[(b * CC + c) * SS + s] = acc * (1.f / (float)T_);
}

// --------------------- loss: bitonic top-k ---------------------------------
__device__ inline void sort_desc256(float* d, int tid)
{
#pragma unroll
    for (int k = 2; k <= 256; k <<= 1) {
        for (int j = k >> 1; j > 0; j >>= 1) {
            __syncthreads();
            int ixj = tid ^ j;
            if (ixj > tid) {
                float a = d[tid], b = d[ixj];
                bool up = ((tid & k) == 0);
                if ((a < b) == up) { d[tid] = b; d[ixj] = a; }
            }
        }
    }
    __syncthreads();
}

__global__ void loss_kernel(const int* __restrict__ y, float* __restrict__ out)
{
    __shared__ float buf[256];
    const int tid = threadIdx.x;
    float total = 0.f;
    float negmean = 0.f;
    for (int b = 0; b < B_; b++) {
        const int yb = y[b];
        const int c0 = (yb == 0) ? 1 : 0;
        const int c1 = (yb == 2) ? 1 : 2;
        const int cneg = (tid < 128) ? c0 : c1;
        buf[tid] = g_att[(b * CC + cneg) * SS + (tid & 127)];
        __syncthreads();
        sort_desc256(buf, tid);
        if (tid == 0) {
            float s = 0.f;
            for (int i = 0; i < 100; i++) s += buf[i];
            negmean = s * 0.01f;
        }
        __syncthreads();
        buf[tid] = (tid < 128) ? g_att[(b * CC + yb) * SS + tid] : -3.4e38f;
        __syncthreads();
        sort_desc256(buf, tid);
        if (tid == 0) {
            float s = 0.f;
            for (int i = 0; i < 100; i++) s += buf[i];
            total += expf(-s * 0.01f + negmean);
        }
        __syncthreads();
    }
    if (tid == 0) out[OFF_LOSS] = total / (float)B_;
}

// ---------------------------------------------------------------------------
extern "C" void kernel_launch(void* const* d_in, const int* in_sizes, int n_in,
                              void* d_out, int out_size)
{
    const float* x       = (const float*)d_in[0];
    const int*   y       = (const int*)  d_in[1];
    const float* W1      = (const float*)d_in[2];
    const float* b1      = (const float*)d_in[3];
    const float* W2      = (const float*)d_in[4];
    const float* b2      = (const float*)d_in[5];
    const float* W3      = (const float*)d_in[6];
    const float* b3      = (const float*)d_in[7];
    const float* proxies = (const float*)d_in[8];
    const float* eps     = (const float*)d_in[9];
    float* out = (float*)d_out;

    __half *x16, *h1, *h2, *w1, *w2, *w3;
    cudaGetSymbolAddress((void**)&x16, g_x16);
    cudaGetSymbolAddress((void**)&h1,  g_h1);
    cudaGetSymbolAddress((void**)&h2,  g_h2);
    cudaGetSymbolAddress((void**)&w1,  g_w1);
    cudaGetSymbolAddress((void**)&w2,  g_w2);
    cudaGetSymbolAddress((void**)&w3,  g_w3);
    float* z = out + OFF_Z;

    const int SMEM = NSTG * STGB;   // 92160 B
    cudaFuncSetAttribute(gemm_f16<0>, cudaFuncAttributeMaxDynamicSharedMemorySize, SMEM);
    cudaFuncSetAttribute(gemm_f16<1>, cudaFuncAttributeMaxDynamicSharedMemorySize, SMEM);

    // conversions
    conv_x<<<(MTOT * XD / 4) / 256, 256>>>(x, x16);
    conv_w<<<(XD * HD + 255) / 256, 256>>>(W1, w1, XD, HD);
    conv_w<<<(HD * HD + 255) / 256, 256>>>(W2, w2, HD, HD);
    conv_w<<<(HD * ZD + 255) / 256, 256>>>(W3, w3, HD, ZD);

    // encoder (tensor cores, single-pass fp16)
    gemm_f16<0><<<dim3(HD / 256, MTOT / 128), 256, SMEM>>>(x16, w1, b1, h1, nullptr, HD, XD);
    gemm_f16<0><<<dim3(HD / 256, MTOT / 128), 256, SMEM>>>(h1,  w2, b2, h2, nullptr, HD, HD);
    gemm_f16<1><<<dim3(ZD / 256, MTOT / 128), 256, SMEM>>>(h2,  w3, b3, nullptr, z, ZD, HD);

    // reductions + proxy side
    colreduce_partial<<<dim3(B_, 32), ZD>>>(z);
    colreduce_final<<<B_, ZD>>>();
    proxy_prep<<<CC, ZD>>>(proxies, eps, out);
    att_kernel<<<dim3(B_, CC), SS>>>(eps);
    loss_kernel<<<1, 256>>>(y, out);
}

// round 11
// speedup vs baseline: 3.9536x; 1.0750x over previous
#include <cuda_runtime.h>
#include <cuda_fp16.h>
#include <cstdint>
#include <math.h>

// ---------------------------------------------------------------------------
//   x: (16,4096,512)  y:(16) int32
//   W1:(512,512) b1:(512) W2:(512,512) b2:(512) W3:(512,256) b3:(256)
//   proxies:(3,512)  eps_proxy:(3,128,256)
// Outputs (f32 concat): mu(12288) sigma(12288) loss(1) z(16*4096*256)
// ---------------------------------------------------------------------------
#define B_   16
#define T_   4096
#define XD   512
#define ZD   256
#define HD   512
#define CC   3
#define SS   128
#define MTOT (B_*T_)        // 65536
#define OFF_MU    0
#define OFF_SIG   12288
#define OFF_LOSS  24576
#define OFF_Z     24577

// ------------------------- scratch (static device) -------------------------
__device__ __half g_x16[(size_t)MTOT * XD];
__device__ __half g_h1 [(size_t)MTOT * HD];
__device__ __half g_h2 [(size_t)MTOT * HD];
__device__ __half g_w1 [HD * XD];        // [N][K] transposed
__device__ __half g_w2 [HD * HD];
__device__ __half g_w3 [ZD * HD];
__device__ float g_ps  [B_ * 32 * ZD];
__device__ float g_ps2 [B_ * 32 * ZD];
__device__ float g_zsum[B_ * ZD];
__device__ float g_mu  [CC * ZD];
__device__ float g_sg  [CC * ZD];
__device__ float g_invn[CC * ZD];
__device__ float g_att [B_ * CC * SS];

// ------------------------- helpers -----------------------------------------
__device__ __forceinline__ void cpasync16(void* s, const void* g) {
    uint32_t sa = (uint32_t)__cvta_generic_to_shared(s);
    asm volatile("cp.async.cg.shared.global [%0], [%1], 16;\n" :: "r"(sa), "l"(g));
}
__device__ __forceinline__ void cp_commit() { asm volatile("cp.async.commit_group;\n"); }
__device__ __forceinline__ void cp_wait1()  { asm volatile("cp.async.wait_group 1;\n"); }
__device__ __forceinline__ void cp_wait0()  { asm volatile("cp.async.wait_group 0;\n"); }

__device__ __forceinline__ void ldmx4(uint32_t& r0, uint32_t& r1, uint32_t& r2, uint32_t& r3,
                                      const __half* p) {
    uint32_t sa = (uint32_t)__cvta_generic_to_shared(p);
    asm volatile("ldmatrix.sync.aligned.m8n8.x4.shared.b16 {%0,%1,%2,%3}, [%4];\n"
                 : "=r"(r0), "=r"(r1), "=r"(r2), "=r"(r3) : "r"(sa));
}
__device__ __forceinline__ void mma16816(float* d, const uint32_t* a, const uint32_t* b) {
    asm volatile("mma.sync.aligned.m16n8k16.row.col.f32.f16.f16.f32 "
                 "{%0,%1,%2,%3}, {%4,%5,%6,%7}, {%8,%9}, {%0,%1,%2,%3};\n"
                 : "+f"(d[0]), "+f"(d[1]), "+f"(d[2]), "+f"(d[3])
                 : "r"(a[0]), "r"(a[1]), "r"(a[2]), "r"(a[3]), "r"(b[0]), "r"(b[1]));
}

// ------------------------- fp16 GEMM (occupancy-2) --------------------------
// C[M,N] = A[M,K] @ W[N,K]^T + bias.  BM=128 BN=128 BK=32, 8 warps of 64x32.
// 2 CTAs/SM (4 warps/SMSP) for latency hiding.
// OUTMODE 0: relu, write fp16.  OUTMODE 1: no relu, write fp32.
#define SA    40                       // padded row stride (half elems) = 80 B
#define A_SUB (128 * SA * 2)           // 10240 B
#define B_SUB (128 * SA * 2)           // 10240 B
#define STGB  (A_SUB + B_SUB)          // 20480 B per stage
#define NSTG  3

template<int OUTMODE>
__global__ __launch_bounds__(256, 2)
void mlp_gemm_occ2(const __half* __restrict__ A, const __half* __restrict__ Bw,
                   const float* __restrict__ bias,
                   __half* __restrict__ Oh, float* __restrict__ Of, int N, int K)
{
    extern __shared__ __align__(16) char sm[];

    const int tid  = threadIdx.x;
    const int lane = tid & 31;
    const int wid  = tid >> 5;
    const int m0w  = (wid >> 2) * 64;      // warp row offset (0 / 64)
    const int n0w  = (wid & 3) * 32;       // warp col offset (0..96)
    const int row0 = blockIdx.y * 128;
    const int col0 = blockIdx.x * 128;

    float acc[4][4][4];
#pragma unroll
    for (int i = 0; i < 4; i++)
#pragma unroll
        for (int j = 0; j < 4; j++)
#pragma unroll
            for (int r = 0; r < 4; r++) acc[i][j][r] = 0.f;

    auto stage_ptr = [&](int s) { return sm + (size_t)s * STGB; };

    auto load_stage = [&](int s, int kc) {
        char* sb = stage_ptr(s);
        const int k0 = kc * 32;
#pragma unroll
        for (int i = 0; i < 2; i++) {
            int c = tid + i * 256;
            int r = c >> 2, g = (c & 3) * 16;
            uint32_t so = (uint32_t)(r * (SA * 2) + g);
            cpasync16(sb + so,         A  + (size_t)(row0 + r) * K + k0 + g / 2);
            cpasync16(sb + A_SUB + so, Bw + (size_t)(col0 + r) * K + k0 + g / 2);
        }
        cp_commit();
    };

    const int nk = K / 32;                 // 16 or 8
    load_stage(0, 0);
    load_stage(1, 1);

    for (int kc = 0; kc < nk; kc++) {
        if (kc + 2 < nk) cp_wait1(); else cp_wait0();
        __syncthreads();
        if (kc + 2 < nk) load_stage((kc + 2) % NSTG, kc + 2);

        char* sb = stage_ptr(kc % NSTG);
        const __half* smA = (const __half*)(sb);
        const __half* smB = (const __half*)(sb + A_SUB);

#pragma unroll
        for (int ks = 0; ks < 2; ks++) {
            const int k0s = ks * 16;
            uint32_t a[4][4], b[4][2];
#pragma unroll
            for (int mi = 0; mi < 4; mi++) {
                const int off = (m0w + mi * 16 + (lane & 15)) * SA + k0s + (lane >> 4) * 8;
                ldmx4(a[mi][0], a[mi][1], a[mi][2], a[mi][3], smA + off);
            }
#pragma unroll
            for (int nt = 0; nt < 2; nt++) {
                const int off = (n0w + nt * 16 + (lane & 7) + ((lane >> 4) << 3)) * SA
                              + k0s + (((lane >> 3) & 1) << 3);
                uint32_t r0, r1, r2, r3;
                ldmx4(r0, r1, r2, r3, smB + off);
                b[nt * 2][0] = r0; b[nt * 2][1] = r1;
                b[nt * 2 + 1][0] = r2; b[nt * 2 + 1][1] = r3;
            }
#pragma unroll
            for (int mi = 0; mi < 4; mi++)
#pragma unroll
                for (int nj = 0; nj < 4; nj++)
                    mma16816(acc[mi][nj], a[mi], b[nj]);
        }
        __syncthreads();
    }

    // ---------------- epilogue ----------------
    float bv[4][2];
#pragma unroll
    for (int nj = 0; nj < 4; nj++) {
        const int c = col0 + n0w + nj * 8 + (lane & 3) * 2;
        bv[nj][0] = bias[c]; bv[nj][1] = bias[c + 1];
    }
#pragma unroll
    for (int mi = 0; mi < 4; mi++) {
        const int r0 = row0 + m0w + mi * 16 + (lane >> 2);
        const int r1 = r0 + 8;
#pragma unroll
        for (int nj = 0; nj < 4; nj++) {
            const int c = col0 + n0w + nj * 8 + (lane & 3) * 2;
            float v00 = acc[mi][nj][0] + bv[nj][0];
            float v01 = acc[mi][nj][1] + bv[nj][1];
            float v10 = acc[mi][nj][2] + bv[nj][0];
            float v11 = acc[mi][nj][3] + bv[nj][1];
            if (OUTMODE == 0) {
                v00 = fmaxf(v00, 0.f); v01 = fmaxf(v01, 0.f);
                v10 = fmaxf(v10, 0.f); v11 = fmaxf(v11, 0.f);
                __half2 h0, h1;
                h0.x = __float2half(v00); h0.y = __float2half(v01);
                h1.x = __float2half(v10); h1.y = __float2half(v11);
                *reinterpret_cast<__half2*>(Oh + (size_t)r0 * N + c) = h0;
                *reinterpret_cast<__half2*>(Oh + (size_t)r1 * N + c) = h1;
            } else {
                Of[(size_t)r0 * N + c]     = v00;
                Of[(size_t)r0 * N + c + 1] = v01;
                Of[(size_t)r1 * N + c]     = v10;
                Of[(size_t)r1 * N + c + 1] = v11;
            }
        }
    }
}

// ------------------- conversion kernels ------------------------------------
__global__ void conv_x(const float* __restrict__ x, __half* __restrict__ x16)
{
    const size_t i = (size_t)blockIdx.x * blockDim.x + threadIdx.x;   // per 4 elems
    float4 v = reinterpret_cast<const float4*>(x)[i];
    __half2 h0, h1;
    h0.x = __float2half(v.x); h0.y = __float2half(v.y);
    h1.x = __float2half(v.z); h1.y = __float2half(v.w);
    reinterpret_cast<__half2*>(x16)[i * 2]     = h0;
    reinterpret_cast<__half2*>(x16)[i * 2 + 1] = h1;
}

// W[K,N] fp32 -> Wt[N,K] fp16 (coalesced reads)
__global__ void conv_w(const float* __restrict__ W, __half* __restrict__ Wt,
                       int K, int N)
{
    const int i = blockIdx.x * blockDim.x + threadIdx.x;
    if (i >= K * N) return;
    const int k = i / N, n = i % N;
    Wt[(size_t)n * K + k] = __float2half(W[i]);
}

// --------------------- column reductions over t (per b,k) ------------------
__global__ void colreduce_partial(const float* __restrict__ z)
{
    const int b  = blockIdx.x;
    const int tc = blockIdx.y;
    const int k  = threadIdx.x;
    const float* base = z + ((size_t)b * T_ + (size_t)tc * 128) * ZD + k;
    float s = 0.f, s2 = 0.f;
#pragma unroll 4
    for (int i = 0; i < 128; i++) {
        float v = base[(size_t)i * ZD];
        s += v; s2 += v * v;
    }
    g_ps [(b * 32 + tc) * ZD + k] = s;
    g_ps2[(b * 32 + tc) * ZD + k] = s2;
}

__global__ void colreduce_final()
{
    const int b = blockIdx.x, k = threadIdx.x;
    float s = 0.f, s2 = 0.f;
#pragma unroll
    for (int tc = 0; tc < 32; tc++) {
        s  += g_ps [(b * 32 + tc) * ZD + k];
        s2 += g_ps2[(b * 32 + tc) * ZD + k];
    }
    float n = fmaxf(sqrtf(s2), 1e-12f);
    g_zsum[b * ZD + k] = s / n;
}

// --------------------- proxy prep ------------------------------------------
__global__ void proxy_prep(const float* __restrict__ proxies,
                           const float* __restrict__ eps,
                           float* __restrict__ out)
{
    const int c = blockIdx.x;
    const int k = threadIdx.x;
    const float m = proxies[c * 512 + k];
    const float p = proxies[c * 512 + ZD + k];
    const float sg = fmaxf(p, 0.f) + log1pf(expf(-fabsf(p)));
    g_mu[c * ZD + k] = m;
    g_sg[c * ZD + k] = sg;
    float acc = 0.f;
    const float* e = eps + ((size_t)c * SS) * ZD + k;
#pragma unroll 4
    for (int s = 0; s < SS; s++) {
        float v = m + sg * e[(size_t)s * ZD];
        acc += v * v;
    }
    g_invn[c * ZD + k] = 1.f / fmaxf(sqrtf(acc), 1e-12f);
    for (int b = 0; b < B_; b++) {
        out[OFF_MU  + (b * CC + c) * ZD + k] = m;
        out[OFF_SIG + (b * CC + c) * ZD + k] = sg;
    }
}

// --------------------- att[b,c,s] ------------------------------------------
__global__ void att_kernel(const float* __restrict__ eps)
{
    const int b = blockIdx.x;
    const int c = blockIdx.y;
    const int s = threadIdx.x;
    const float* e = eps + ((size_t)c * SS + s) * ZD;
    float acc = 0.f;
#pragma unroll 8
    for (int k = 0; k < ZD; k++) {
        float zp = (g_mu[c * ZD + k] + g_sg[c * ZD + k] * e[k]) * g_invn[c * ZD + k];
        acc += g_zsum[b * ZD + k] * zp;
    }
    g_att[(b * CC + c) * SS + s] = acc * (1.f / (float)T_);
}

// --------------------- loss: bitonic top-k ---------------------------------
__device__ inline void sort_desc256(float* d, int tid)
{
#pragma unroll
    for (int k = 2; k <= 256; k <<= 1) {
        for (int j = k >> 1; j > 0; j >>= 1) {
            __syncthreads();
            int ixj = tid ^ j;
            if (ixj > tid) {
                float a = d[tid], b = d[ixj];
                bool up = ((tid & k) == 0);
                if ((a < b) == up) { d[tid] = b; d[ixj] = a; }
            }
        }
    }
    __syncthreads();
}

__global__ void loss_kernel(const int* __restrict__ y, float* __restrict__ out)
{
    __shared__ float buf[256];
    const int tid = threadIdx.x;
    float total = 0.f;
    float negmean = 0.f;
    for (int b = 0; b < B_; b++) {
        const int yb = y[b];
        const int c0 = (yb == 0) ? 1 : 0;
        const int c1 = (yb == 2) ? 1 : 2;
        const int cneg = (tid < 128) ? c0 : c1;
        buf[tid] = g_att[(b * CC + cneg) * SS + (tid & 127)];
        __syncthreads();
        sort_desc256(buf, tid);
        if (tid == 0) {
            float s = 0.f;
            for (int i = 0; i < 100; i++) s += buf[i];
            negmean = s * 0.01f;
        }
        __syncthreads();
        buf[tid] = (tid < 128) ? g_att[(b * CC + yb) * SS + tid] : -3.4e38f;
        __syncthreads();
        sort_desc256(buf, tid);
        if (tid == 0) {
            float s = 0.f;
            for (int i = 0; i < 100; i++) s += buf[i];
            total += expf(-s * 0.01f + negmean);
        }
        __syncthreads();
    }
    if (tid == 0) out[OFF_LOSS] = total / (float)B_;
}

// ---------------------------------------------------------------------------
extern "C" void kernel_launch(void* const* d_in, const int* in_sizes, int n_in,
                              void* d_out, int out_size)
{
    const float* x       = (const float*)d_in[0];
    const int*   y       = (const int*)  d_in[1];
    const float* W1      = (const float*)d_in[2];
    const float* b1      = (const float*)d_in[3];
    const float* W2      = (const float*)d_in[4];
    const float* b2      = (const float*)d_in[5];
    const float* W3      = (const float*)d_in[6];
    const float* b3      = (const float*)d_in[7];
    const float* proxies = (const float*)d_in[8];
    const float* eps     = (const float*)d_in[9];
    float* out = (float*)d_out;

    __half *x16, *h1, *h2, *w1, *w2, *w3;
    cudaGetSymbolAddress((void**)&x16, g_x16);
    cudaGetSymbolAddress((void**)&h1,  g_h1);
    cudaGetSymbolAddress((void**)&h2,  g_h2);
    cudaGetSymbolAddress((void**)&w1,  g_w1);
    cudaGetSymbolAddress((void**)&w2,  g_w2);
    cudaGetSymbolAddress((void**)&w3,  g_w3);
    float* z = out + OFF_Z;

    const int SMEM = NSTG * STGB;   // 61440 B  (2 CTAs/SM)
    cudaFuncSetAttribute(mlp_gemm_occ2<0>, cudaFuncAttributeMaxDynamicSharedMemorySize, SMEM);
    cudaFuncSetAttribute(mlp_gemm_occ2<1>, cudaFuncAttributeMaxDynamicSharedMemorySize, SMEM);

    // conversions
    conv_x<<<(MTOT * XD / 4) / 256, 256>>>(x, x16);
    conv_w<<<(XD * HD + 255) / 256, 256>>>(W1, w1, XD, HD);
    conv_w<<<(HD * HD + 255) / 256, 256>>>(W2, w2, HD, HD);
    conv_w<<<(HD * ZD + 255) / 256, 256>>>(W3, w3, HD, ZD);

    // encoder (tensor cores, single-pass fp16, 2 CTAs/SM)
    mlp_gemm_occ2<0><<<dim3(HD / 128, MTOT / 128), 256, SMEM>>>(x16, w1, b1, h1, nullptr, HD, XD);
    mlp_gemm_occ2<0><<<dim3(HD / 128, MTOT / 128), 256, SMEM>>>(h1,  w2, b2, h2, nullptr, HD, HD);
    mlp_gemm_occ2<1><<<dim3(ZD / 128, MTOT / 128), 256, SMEM>>>(h2,  w3, b3, nullptr, z, ZD, HD);

    // reductions + proxy side
    colreduce_partial<<<dim3(B_, 32), ZD>>>(z);
    colreduce_final<<<B_, ZD>>>();
    proxy_prep<<<CC, ZD>>>(proxies, eps, out);
    att_kernel<<<dim3(B_, CC), SS>>>(eps);
    loss_kernel<<<1, 256>>>(y, out);
}